// round 6
// baseline (speedup 1.0000x reference)
#include <cuda_runtime.h>
#include <math.h>
#include <float.h>

#define BB 8
#define TT 4096
#define DD 256
#define MM 1024
#define CTX 7
#define TJ 4102            // T-1+CTX
#define KC (DD*CTX)        // 1792
#define NROWS (BB*TT)      // 32768
#define QOUT (NROWS*DD)    // 8388608
#define OUT_NEED (QOUT + 2 + NROWS)

// ---------------- scratch (static device memory; no runtime allocation) ----
__device__ float g_cn[BB*DD*TJ];        // noisy padded context input [b][d][j]
__device__ float g_ctxT[NROWS*DD];      // conv output, [b][t][o] layout
__device__ float g_cur[NROWS*DD];       // fuse1 output rows [bt][d]
__device__ float g_z[(size_t)NROWS*MM]; // z = 2*cur.E - |E|^2  (dm + row const)
__device__ float g_wT[KC*DD];           // w_ctx transposed [k][o]
__device__ float g_wf1T[2*DD*DD];       // w_f1 transposed [c][o]
__device__ float g_wf2T[2*DD*DD];
__device__ float g_ET[DD*MM];           // E transposed [d][m]
__device__ float g_e2[MM];              // |E_m|^2
__device__ float g_coef[BB];            // noise coefficient per batch
__device__ int   g_idx[NROWS];          // gumbel argmax indices
__device__ float g_avgp[256*MM];        // per-block softmax partial sums
__device__ int   g_hardp[256*MM];       // per-block hard histograms
__device__ float g_terms[2*MM];         // entropy terms (soft, hard)

// ---------------- K0: batch RMS scale + epo decode ------------------------
__global__ void k_scale(const float* __restrict__ x, const int* __restrict__ epo_raw)
{
    int b = blockIdx.x;
    const float* xb = x + (size_t)b*TT*DD;
    const int N = (TT-1)*DD;
    double s = 0.0;
    for (int i = threadIdx.x; i < N; i += 256) { float v = xb[i]; s += (double)v*v; }
    __shared__ double sh[256];
    sh[threadIdx.x] = s; __syncthreads();
    for (int st = 128; st; st >>= 1) {
        if (threadIdx.x < st) sh[threadIdx.x] += sh[threadIdx.x+st];
        __syncthreads();
    }
    if (threadIdx.x == 0) {
        int w = epo_raw[0];
        float epo = (w >= 0 && w < 1000000) ? (float)w : __int_as_float(w);
        float scale = sqrtf((float)(sh[0] / ((double)DD * (double)TJ)));
        g_coef[b] = 0.5f * scale * powf(0.5f, epo * 0.1f);
    }
}

// ---------------- K1: build noisy padded context input (transpose x) -------
__global__ void k_cn(const float* __restrict__ x, const float* __restrict__ noise)
{
    __shared__ float tile[32][33];
    int b  = blockIdx.z;
    int j0 = blockIdx.x * 32;
    int d0 = blockIdx.y * 32;
    int tx = threadIdx.x, ty = threadIdx.y;      // (32, 8)
    int t0 = j0 - CTX;
    const float* xb = x + (size_t)b*TT*DD;
#pragma unroll
    for (int r = 0; r < 4; r++) {
        int t = t0 + ty + r*8;
        tile[ty + r*8][tx] = (t >= 0 && t < TT-1) ? xb[(size_t)t*DD + d0 + tx] : 0.0f;
    }
    __syncthreads();
    float coef = g_coef[b];
    const float* nb = noise + (size_t)b*DD*TJ;
    float*       cb = g_cn  + (size_t)b*DD*TJ;
    int j = j0 + tx;
    if (j < TJ) {
#pragma unroll
        for (int r = 0; r < 4; r++) {
            int d = d0 + ty + r*8;
            cb[(size_t)d*TJ + j] = tile[tx][ty + r*8] + coef * nb[(size_t)d*TJ + j];
        }
    }
}

// ---------------- small weight transposes ---------------------------------
__global__ void k_prep_w(const float* __restrict__ wctx,
                         const float* __restrict__ wf1,
                         const float* __restrict__ wf2)
{
    int i = blockIdx.x * 256 + threadIdx.x;
    if (i < KC*DD) {
        int k = i / DD, o = i - k*DD;
        g_wT[i] = wctx[(size_t)o*KC + k];
    }
    if (i < 2*DD*DD) {
        int c = i / DD, o = i - c*DD;
        g_wf1T[i] = wf1[(size_t)o*(2*DD) + c];
        g_wf2T[i] = wf2[(size_t)o*(2*DD) + c];
    }
}

__global__ void k_prep_E(const float* __restrict__ E)
{
    int i = blockIdx.x * 256 + threadIdx.x;
    if (i < DD*MM) {
        int d = i / MM, m = i - d*MM;
        g_ET[i] = E[(size_t)m*DD + d];
    }
}

__global__ void k_e2(const float* __restrict__ E)
{
    int lane = threadIdx.x & 31, w = threadIdx.x >> 5;
    int m = blockIdx.x * 8 + w;
    const float* row = E + (size_t)m*DD;
    double s = 0.0;
    for (int k = lane; k < DD; k += 32) { float v = row[k]; s += (double)v*v; }
#pragma unroll
    for (int off = 16; off; off >>= 1) s += __shfl_down_sync(0xffffffffu, s, off);
    if (lane == 0) g_e2[m] = (float)s;
}

// ---------------- K3: context conv as GEMM (M=t, N=o, K=(i,h)) -------------
#define FMA16() do { \
    acc[0][0] += av.x*bv.x; acc[0][1] += av.x*bv.y; acc[0][2] += av.x*bv.z; acc[0][3] += av.x*bv.w; \
    acc[1][0] += av.y*bv.x; acc[1][1] += av.y*bv.y; acc[1][2] += av.y*bv.z; acc[1][3] += av.y*bv.w; \
    acc[2][0] += av.z*bv.x; acc[2][1] += av.z*bv.y; acc[2][2] += av.z*bv.z; acc[2][3] += av.z*bv.w; \
    acc[3][0] += av.w*bv.x; acc[3][1] += av.w*bv.y; acc[3][2] += av.w*bv.z; acc[3][3] += av.w*bv.w; } while(0)

__global__ void __launch_bounds__(256) k_conv()
{
    __shared__ float As[16][68];
    __shared__ float Bs[16][68];
    int b  = blockIdx.z;
    int t0 = blockIdx.x * 64;
    int o0 = blockIdx.y * 64;
    int tid = threadIdx.x;
    int lt = tid & 63, lk = tid >> 6;          // loader: element-fast, 4 k-rows/pass
    int tx = tid & 15, ty = tid >> 4;
    const float* cnb = g_cn + (size_t)b*DD*TJ;
    float acc[4][4] = {};
    for (int k0 = 0; k0 < KC; k0 += 16) {
#pragma unroll
        for (int p = 0; p < 4; p++) {
            int kk = lk + p*4;
            int k = k0 + kk;
            int i = k / 7, h = k - i*7;
            As[kk][lt] = cnb[(size_t)i*TJ + t0 + lt + h];
            Bs[kk][lt] = g_wT[(size_t)k*DD + o0 + lt];
        }
        __syncthreads();
#pragma unroll
        for (int kk = 0; kk < 16; kk++) {
            float4 av = *reinterpret_cast<const float4*>(&As[kk][ty*4]);
            float4 bv = *reinterpret_cast<const float4*>(&Bs[kk][tx*4]);
            FMA16();
        }
        __syncthreads();
    }
    float* ob = g_ctxT + ((size_t)b*TT + t0)*DD + o0;
#pragma unroll
    for (int i = 0; i < 4; i++) {
        float4 v = make_float4(acc[i][0], acc[i][1], acc[i][2], acc[i][3]);
        *reinterpret_cast<float4*>(&ob[(size_t)(ty*4 + i)*DD + tx*4]) = v;
    }
}

// ---------------- K fuse1/fuse2: 1x1 conv + PReLU --------------------------
// mode 0: A = [x | ctxT] -> g_cur (slope a1)
// mode 1: A = [E[idx] | ctxT] -> d_out quantized (slope a2)
__global__ void __launch_bounds__(256) k_fuse(const float* __restrict__ x,
                                              const float* __restrict__ E,
                                              const float* __restrict__ a_ptr,
                                              float* __restrict__ outq, int mode)
{
    __shared__ float As[16][68];
    __shared__ float Bs[16][68];
    __shared__ int sIdx[64];
    int b  = blockIdx.z;
    int t0 = blockIdx.x * 64;
    int o0 = blockIdx.y * 64;
    int tid = threadIdx.x;
    int aK = tid & 15, aT = tid >> 4;   // A loader: c-fast (coalesced on row-major A)
    int bO = tid & 63, bK = tid >> 6;   // B loader: o-fast
    int tx = tid & 15, ty = tid >> 4;
    const float* wT = mode ? g_wf2T : g_wf1T;
    if (mode && tid < 64) sIdx[tid] = g_idx[b*TT + t0 + tid];
    __syncthreads();
    const float* ctxb = g_ctxT + ((size_t)b*TT + t0)*DD;
    const float* xb   = x      + ((size_t)b*TT + t0)*DD;
    float acc[4][4] = {};
    for (int k0 = 0; k0 < 2*DD; k0 += 16) {
        if (k0 < DD) {
            int c = k0 + aK;
            if (mode == 0) {
#pragma unroll
                for (int p = 0; p < 4; p++) {
                    int tm = aT + p*16;
                    As[aK][tm] = xb[(size_t)tm*DD + c];
                }
            } else {
#pragma unroll
                for (int p = 0; p < 4; p++) {
                    int tm = aT + p*16;
                    As[aK][tm] = E[(size_t)sIdx[tm]*DD + c];
                }
            }
        } else {
            int c = k0 - DD + aK;
#pragma unroll
            for (int p = 0; p < 4; p++) {
                int tm = aT + p*16;
                As[aK][tm] = ctxb[(size_t)tm*DD + c];
            }
        }
#pragma unroll
        for (int p = 0; p < 4; p++) {
            int kk = bK + p*4;
            Bs[kk][bO] = wT[(size_t)(k0 + kk)*DD + o0 + bO];
        }
        __syncthreads();
#pragma unroll
        for (int kk = 0; kk < 16; kk++) {
            float4 av = *reinterpret_cast<const float4*>(&As[kk][ty*4]);
            float4 bv = *reinterpret_cast<const float4*>(&Bs[kk][tx*4]);
            FMA16();
        }
        __syncthreads();
    }
    float a = *a_ptr;
    float* ob = (mode ? outq : g_cur) + ((size_t)b*TT + t0)*DD + o0;
#pragma unroll
    for (int i = 0; i < 4; i++) {
        float4 v;
        float r;
        r = acc[i][0]; v.x = (r >= 0.f) ? r : a*r;
        r = acc[i][1]; v.y = (r >= 0.f) ? r : a*r;
        r = acc[i][2]; v.z = (r >= 0.f) ? r : a*r;
        r = acc[i][3]; v.w = (r >= 0.f) ? r : a*r;
        *reinterpret_cast<float4*>(&ob[(size_t)(ty*4 + i)*DD + tx*4]) = v;
    }
}

// ---------------- K4a: distance GEMM -> z = 2*cur.E - |E|^2 ---------------
__global__ void __launch_bounds__(256) k_dist()
{
    __shared__ float As[16][68];
    __shared__ float Bs[16][68];
    int r0 = blockIdx.x * 64;
    int m0 = blockIdx.y * 64;
    int tid = threadIdx.x;
    int aK = tid & 15, aT = tid >> 4;
    int bO = tid & 63, bK = tid >> 6;
    int tx = tid & 15, ty = tid >> 4;
    float acc[4][4] = {};
    for (int k0 = 0; k0 < DD; k0 += 16) {
#pragma unroll
        for (int p = 0; p < 4; p++) {
            int rm = aT + p*16;
            As[aK][rm] = g_cur[(size_t)(r0 + rm)*DD + k0 + aK];
        }
#pragma unroll
        for (int p = 0; p < 4; p++) {
            int kk = bK + p*4;
            Bs[kk][bO] = g_ET[(size_t)(k0 + kk)*MM + m0 + bO];
        }
        __syncthreads();
#pragma unroll
        for (int kk = 0; kk < 16; kk++) {
            float4 av = *reinterpret_cast<const float4*>(&As[kk][ty*4]);
            float4 bv = *reinterpret_cast<const float4*>(&Bs[kk][tx*4]);
            FMA16();
        }
        __syncthreads();
    }
#pragma unroll
    for (int i = 0; i < 4; i++) {
        float4 v;
        v.x = 2.0f*acc[i][0] - g_e2[m0 + tx*4 + 0];
        v.y = 2.0f*acc[i][1] - g_e2[m0 + tx*4 + 1];
        v.z = 2.0f*acc[i][2] - g_e2[m0 + tx*4 + 2];
        v.w = 2.0f*acc[i][3] - g_e2[m0 + tx*4 + 3];
        *reinterpret_cast<float4*>(&g_z[(size_t)(r0 + ty*4 + i)*MM + m0 + tx*4]) = v;
    }
}

// ---------------- warp helpers --------------------------------------------
__device__ __forceinline__ void wargmax(float& v, int& i)
{
#pragma unroll
    for (int off = 16; off; off >>= 1) {
        float ov = __shfl_down_sync(0xffffffffu, v, off);
        int   oi = __shfl_down_sync(0xffffffffu, i, off);
        if (ov > v || (ov == v && oi < i)) { v = ov; i = oi; }
    }
}
__device__ __forceinline__ float wsum(float v)
{
#pragma unroll
    for (int off = 16; off; off >>= 1) v += __shfl_down_sync(0xffffffffu, v, off);
    return v;
}

// ---------------- K4b: per-row argmax / softmax / gumbel -------------------
__global__ void __launch_bounds__(256) k_stats(const float* __restrict__ gu,
                                               float* __restrict__ out_inds,
                                               int write_inds)
{
    __shared__ float sV[8];  __shared__ int sI[8];
    __shared__ float sV2[8]; __shared__ int sI2[8];
    __shared__ float sS[8];
    __shared__ float sMax;   __shared__ int sHard;
    __shared__ float sSum;
    __shared__ int sHist[MM];
    int tid = threadIdx.x;
    int lane = tid & 31, w = tid >> 5;
#pragma unroll
    for (int q = 0; q < 4; q++) sHist[tid*4 + q] = 0;
    float acc0 = 0.f, acc1 = 0.f, acc2 = 0.f, acc3 = 0.f;
    int base = blockIdx.x * 128;
    __syncthreads();

    for (int r = 0; r < 128; r++) {
        size_t off = (size_t)(base + r)*MM + tid*4;
        float4 z = *reinterpret_cast<const float4*>(g_z + off);
        float4 u = *reinterpret_cast<const float4*>(gu + off);

        // hard argmax (z only), first-max tie break
        float hv = z.x; int hi = tid*4;
        if (z.y > hv) { hv = z.y; hi = tid*4 + 1; }
        if (z.z > hv) { hv = z.z; hi = tid*4 + 2; }
        if (z.w > hv) { hv = z.w; hi = tid*4 + 3; }

        // gumbel-perturbed argmax
        const float lo = 1e-10f, hicl = 1.0f - 1e-7f;
        float y0 = z.x - logf(-logf(fminf(fmaxf(u.x, lo), hicl)));
        float y1 = z.y - logf(-logf(fminf(fmaxf(u.y, lo), hicl)));
        float y2 = z.z - logf(-logf(fminf(fmaxf(u.z, lo), hicl)));
        float y3 = z.w - logf(-logf(fminf(fmaxf(u.w, lo), hicl)));
        float yv = y0; int yi = tid*4;
        if (y1 > yv) { yv = y1; yi = tid*4 + 1; }
        if (y2 > yv) { yv = y2; yi = tid*4 + 2; }
        if (y3 > yv) { yv = y3; yi = tid*4 + 3; }

        float hvr = hv; int hir = hi;  wargmax(hvr, hir);
        float yvr = yv; int yir = yi;  wargmax(yvr, yir);
        if (lane == 0) { sV[w] = hvr; sI[w] = hir; sV2[w] = yvr; sI2[w] = yir; }
        __syncthreads();
        if (w == 0) {
            float v = (lane < 8) ? sV[lane] : -FLT_MAX;
            int   i = (lane < 8) ? sI[lane] : 0x7fffffff;
            wargmax(v, i);
            if (lane == 0) { sMax = v; sHard = i; }
        }
        if (w == 1) {
            float v = (lane < 8) ? sV2[lane] : -FLT_MAX;
            int   i = (lane < 8) ? sI2[lane] : 0x7fffffff;
            wargmax(v, i);
            if (lane == 0) {
                g_idx[base + r] = i;
                if (write_inds) out_inds[base + r] = (float)i;
            }
        }
        __syncthreads();
        if (tid == 0) sHist[sHard]++;
        float mx = sMax;
        float e0 = expf(z.x - mx);
        float e1 = expf(z.y - mx);
        float e2v = expf(z.z - mx);
        float e3 = expf(z.w - mx);
        float s = wsum(e0 + e1 + e2v + e3);
        if (lane == 0) sS[w] = s;
        __syncthreads();
        if (w == 0) {
            float v = (lane < 8) ? sS[lane] : 0.f;
            v = wsum(v);
            if (lane == 0) sSum = v;
        }
        __syncthreads();
        float inv = 1.0f / sSum;
        acc0 += e0*inv; acc1 += e1*inv; acc2 += e2v*inv; acc3 += e3*inv;
        __syncthreads();
    }
    float4 av = make_float4(acc0, acc1, acc2, acc3);
    *reinterpret_cast<float4*>(&g_avgp[blockIdx.x*MM + tid*4]) = av;
    int4 hv4 = make_int4(sHist[tid*4], sHist[tid*4+1], sHist[tid*4+2], sHist[tid*4+3]);
    *reinterpret_cast<int4*>(&g_hardp[blockIdx.x*MM + tid*4]) = hv4;
}

// ---------------- K5a: per-code column reduction + entropy terms -----------
__global__ void k_colred()
{
    int m = blockIdx.x;
    int tid = threadIdx.x;
    __shared__ float shf[256];
    __shared__ int   shi[256];
    shf[tid] = g_avgp[(size_t)tid*MM + m];
    shi[tid] = g_hardp[(size_t)tid*MM + m];
    __syncthreads();
    for (int st = 128; st; st >>= 1) {
        if (tid < st) { shf[tid] += shf[tid+st]; shi[tid] += shi[tid+st]; }
        __syncthreads();
    }
    if (tid == 0) {
        float ap = shf[0] / (float)NROWS;
        float hp = (float)shi[0] / (float)NROWS;
        g_terms[m]      = -ap * log2f(ap + 1e-10f);   // soft
        g_terms[MM + m] = -hp * log2f(hp + 1e-10f);   // hard
    }
}

// ---------------- K5b: final perplexity scalars ----------------------------
__global__ void k_final(float* __restrict__ out, int write_ok)
{
    __shared__ float s1[256], s2[256];
    int tid = threadIdx.x;
    float a = 0.f, b = 0.f;
    for (int m = tid; m < MM; m += 256) { a += g_terms[m]; b += g_terms[MM + m]; }
    s1[tid] = a; s2[tid] = b; __syncthreads();
    for (int st = 128; st; st >>= 1) {
        if (tid < st) { s1[tid] += s1[tid+st]; s2[tid] += s2[tid+st]; }
        __syncthreads();
    }
    if (tid == 0 && write_ok) {
        out[QOUT + 0] = s2[0];  // code_perplexity (hard)
        out[QOUT + 1] = s1[0];  // prob_perplexity (soft)
    }
}

// ---------------- launch ----------------------------------------------------
extern "C" void kernel_launch(void* const* d_in, const int* in_sizes, int n_in,
                              void* d_out, int out_size)
{
    const float* x     = (const float*)d_in[0];
    const float* noise = (const float*)d_in[1];
    const float* gu    = (const float*)d_in[2];
    const int*   epo   = (const int*)  d_in[3];
    const float* E     = (const float*)d_in[4];   // [1, M, D]
    const float* wctx  = (const float*)d_in[5];
    const float* wf1   = (const float*)d_in[6];
    const float* a1    = (const float*)d_in[7];
    const float* wf2   = (const float*)d_in[8];
    const float* a2    = (const float*)d_in[9];
    float* out = (float*)d_out;
    // Defensive: only touch the tail region if the harness buffer is big enough.
    int tail_ok = (out_size >= OUT_NEED) ? 1 : 0;

    k_scale<<<BB, 256>>>(x, epo);
    k_prep_w<<<(KC*DD + 255)/256, 256>>>(wctx, wf1, wf2);
    k_prep_E<<<(DD*MM)/256, 256>>>(E);
    k_e2<<<MM/8, 256>>>(E);
    k_cn<<<dim3((TJ + 31)/32, DD/32, BB), dim3(32, 8)>>>(x, noise);
    k_conv<<<dim3(TT/64, DD/64, BB), 256>>>();
    k_fuse<<<dim3(TT/64, DD/64, BB), 256>>>(x, E, a1, out, 0);
    k_dist<<<dim3(NROWS/64, MM/64), 256>>>();
    k_stats<<<256, 256>>>(gu, out + QOUT + 2, tail_ok);
    k_colred<<<MM, 256>>>();
    k_final<<<1, 256>>>(out, tail_ok);
    k_fuse<<<dim3(TT/64, DD/64, BB), 256>>>(x, E, a2, out, 1);
}

// round 9
// speedup vs baseline: 1.1322x; 1.1322x over previous
#include <cuda_runtime.h>
#include <cuda_bf16.h>
#include <math.h>
#include <float.h>
#include <stdint.h>

#define BB 8
#define TT 4096
#define DD 256
#define MM 1024
#define CTX 7
#define TJ 4102            // T-1+CTX
#define KC (DD*CTX)        // 1792
#define NROWS (BB*TT)      // 32768
#define QOUT (NROWS*DD)    // 8388608
#define OUT_NEED (QOUT + 2 + NROWS)

// ================= global scratch (static; no runtime allocation) ==================
__device__ float g_cn[BB*DD*TJ];              // noisy padded ctx input [b][d][j] (fp32, R6)
__device__ float g_ctxT[NROWS*DD];            // conv output fp32 [bt][o]  (bit-identical z path)
__device__ __nv_bfloat16 g_ctxL[3][NROWS*DD]; // conv output bf16 limbs (fuse2 only)
__device__ float g_cur[NROWS*DD];             // fuse1 output fp32 [bt][d]
__device__ float g_z[(size_t)NROWS*MM];       // z = 2*cur.E - |E|^2
__device__ float g_wT[KC*DD];                 // w_ctx transposed [k][o]
__device__ float g_wf1T[2*DD*DD];             // w_f1 transposed [c][o]
__device__ float g_ET[DD*MM];                 // E transposed [d][m]
__device__ __nv_bfloat16 g_EL[3][MM*DD];      // codebook bf16 limbs [m][d] (fuse2)
__device__ __nv_bfloat16 g_wf2L[3][DD*2*DD];  // wf2 bf16 limbs [o][c] (fuse2)
__device__ float g_e2[MM];
__device__ float g_coef[BB];
__device__ int   g_idx[NROWS];
__device__ float g_avgp[256*MM];
__device__ int   g_hardp[256*MM];
__device__ float g_terms[2*MM];

// Exact 3-limb bf16 split (l0+l1+l2 reproduces the fp32 value to ~2^-24)
__device__ __forceinline__ void split3(float v, __nv_bfloat16& l0, __nv_bfloat16& l1,
                                       __nv_bfloat16& l2)
{
    l0 = __float2bfloat16_rn(v);
    float r = v - __bfloat162float(l0);
    l1 = __float2bfloat16_rn(r);
    float r2 = r - __bfloat162float(l1);
    l2 = __float2bfloat16_rn(r2);
}

// ---------------- K0: batch RMS scale + epo decode (R6 verbatim) -------------------
__global__ void k_scale(const float* __restrict__ x, const int* __restrict__ epo_raw)
{
    int b = blockIdx.x;
    const float* xb = x + (size_t)b*TT*DD;
    const int N = (TT-1)*DD;
    double s = 0.0;
    for (int i = threadIdx.x; i < N; i += 256) { float v = xb[i]; s += (double)v*v; }
    __shared__ double sh[256];
    sh[threadIdx.x] = s; __syncthreads();
    for (int st = 128; st; st >>= 1) {
        if (threadIdx.x < st) sh[threadIdx.x] += sh[threadIdx.x+st];
        __syncthreads();
    }
    if (threadIdx.x == 0) {
        int w = epo_raw[0];
        float epo = (w >= 0 && w < 1000000) ? (float)w : __int_as_float(w);
        float scale = sqrtf((float)(sh[0] / ((double)DD * (double)TJ)));
        g_coef[b] = 0.5f * scale * powf(0.5f, epo * 0.1f);
    }
}

// ---------------- K1: noisy padded ctx input [b][d][j] (R6 verbatim) ---------------
__global__ void k_cn(const float* __restrict__ x, const float* __restrict__ noise)
{
    __shared__ float tile[32][33];
    int b  = blockIdx.z;
    int j0 = blockIdx.x * 32;
    int d0 = blockIdx.y * 32;
    int tx = threadIdx.x, ty = threadIdx.y;      // (32, 8)
    int t0 = j0 - CTX;
    const float* xb = x + (size_t)b*TT*DD;
#pragma unroll
    for (int r = 0; r < 4; r++) {
        int t = t0 + ty + r*8;
        tile[ty + r*8][tx] = (t >= 0 && t < TT-1) ? xb[(size_t)t*DD + d0 + tx] : 0.0f;
    }
    __syncthreads();
    float coef = g_coef[b];
    const float* nb = noise + (size_t)b*DD*TJ;
    float*       cb = g_cn  + (size_t)b*DD*TJ;
    int j = j0 + tx;
    if (j < TJ) {
#pragma unroll
        for (int r = 0; r < 4; r++) {
            int d = d0 + ty + r*8;
            cb[(size_t)d*TJ + j] = tile[tx][ty + r*8] + coef * nb[(size_t)d*TJ + j];
        }
    }
}

// ---------------- weight / codebook prep -------------------------------------------
__global__ void k_prep_w(const float* __restrict__ wctx, const float* __restrict__ wf1)
{
    int i = blockIdx.x * 256 + threadIdx.x;
    if (i < KC*DD) {
        int k = i / DD, o = i - k*DD;
        g_wT[i] = wctx[(size_t)o*KC + k];
    }
    if (i < 2*DD*DD) {
        int c = i / DD, o = i - c*DD;
        g_wf1T[i] = wf1[(size_t)o*(2*DD) + c];
    }
}
__global__ void k_prep_E(const float* __restrict__ E)
{
    int i = blockIdx.x * 256 + threadIdx.x;
    if (i < DD*MM) {
        // fp32 transpose for dist (R6 layout [d][m])
        int d = i / MM, m = i - d*MM;
        g_ET[i] = E[(size_t)m*DD + d];
        // bf16 limbs for fuse2 ([m][d] natural layout)
        __nv_bfloat16 l0, l1, l2; split3(E[i], l0, l1, l2);
        g_EL[0][i] = l0; g_EL[1][i] = l1; g_EL[2][i] = l2;
    }
}
__global__ void k_prep_wf2(const float* __restrict__ wf2)
{
    int i = blockIdx.x * 256 + threadIdx.x;
    if (i < DD*2*DD) {
        __nv_bfloat16 l0, l1, l2; split3(wf2[i], l0, l1, l2);
        g_wf2L[0][i] = l0; g_wf2L[1][i] = l1; g_wf2L[2][i] = l2;
    }
}
__global__ void k_e2(const float* __restrict__ E)
{
    int lane = threadIdx.x & 31, w = threadIdx.x >> 5;
    int m = blockIdx.x * 8 + w;
    const float* row = E + (size_t)m*DD;
    double s = 0.0;
    for (int k = lane; k < DD; k += 32) { float v = row[k]; s += (double)v*v; }
#pragma unroll
    for (int off = 16; off; off >>= 1) s += __shfl_down_sync(0xffffffffu, s, off);
    if (lane == 0) g_e2[m] = (float)s;
}

// ================= retiled fp32 FFMA GEMMs (bit-identical k-order to R6) ===========
// CTA 128(M)x64(N), 256 threads, 8x4 outputs/thread. Per-output accumulation is
// acc += A[k]*B[k] for k ascending — same chain as R6's 4x4 tiles.

#define FMA32() do { \
    acc[0][0] += a0.x*bv.x; acc[0][1] += a0.x*bv.y; acc[0][2] += a0.x*bv.z; acc[0][3] += a0.x*bv.w; \
    acc[1][0] += a0.y*bv.x; acc[1][1] += a0.y*bv.y; acc[1][2] += a0.y*bv.z; acc[1][3] += a0.y*bv.w; \
    acc[2][0] += a0.z*bv.x; acc[2][1] += a0.z*bv.y; acc[2][2] += a0.z*bv.z; acc[2][3] += a0.z*bv.w; \
    acc[3][0] += a0.w*bv.x; acc[3][1] += a0.w*bv.y; acc[3][2] += a0.w*bv.z; acc[3][3] += a0.w*bv.w; \
    acc[4][0] += a1.x*bv.x; acc[4][1] += a1.x*bv.y; acc[4][2] += a1.x*bv.z; acc[4][3] += a1.x*bv.w; \
    acc[5][0] += a1.y*bv.x; acc[5][1] += a1.y*bv.y; acc[5][2] += a1.y*bv.z; acc[5][3] += a1.y*bv.w; \
    acc[6][0] += a1.z*bv.x; acc[6][1] += a1.z*bv.y; acc[6][2] += a1.z*bv.z; acc[6][3] += a1.z*bv.w; \
    acc[7][0] += a1.w*bv.x; acc[7][1] += a1.w*bv.y; acc[7][2] += a1.w*bv.z; acc[7][3] += a1.w*bv.w; } while(0)

// ---------------- conv: ctx[bt][o] = sum_k cn[t + k%7][k/7] * wT[k][o] -------------
__global__ void __launch_bounds__(256) k_conv()
{
    __shared__ float As[16][132];
    __shared__ float Bs[16][68];
    int b  = blockIdx.z;
    int t0 = blockIdx.y * 128;
    int o0 = blockIdx.x * 64;
    int tid = threadIdx.x;
    int tx = tid & 15, ty = tid >> 4;
    int lt = tid & 127, lk = tid >> 7;     // A loader: 128 t x 2 k per pass
    int bo = tid & 63,  bk = tid >> 6;     // B loader: 64 o x 4 k per pass
    const float* cnb = g_cn + (size_t)b*DD*TJ;
    float acc[8][4] = {};
    for (int k0 = 0; k0 < KC; k0 += 16) {
#pragma unroll
        for (int p = 0; p < 8; p++) {
            int kk = lk + p*2;
            int k = k0 + kk;
            int i = k / 7, h = k - i*7;
            As[kk][lt] = cnb[(size_t)i*TJ + t0 + lt + h];
        }
#pragma unroll
        for (int p = 0; p < 4; p++) {
            int kk = bk + p*4;
            Bs[kk][bo] = g_wT[(size_t)(k0 + kk)*DD + o0 + bo];
        }
        __syncthreads();
#pragma unroll
        for (int kk = 0; kk < 16; kk++) {
            float4 a0 = *reinterpret_cast<const float4*>(&As[kk][ty*8]);
            float4 a1 = *reinterpret_cast<const float4*>(&As[kk][ty*8 + 4]);
            float4 bv = *reinterpret_cast<const float4*>(&Bs[kk][tx*4]);
            FMA32();
        }
        __syncthreads();
    }
    // epilogue: fp32 (bit-identical z path) + bf16 limbs (fuse2)
#pragma unroll
    for (int i = 0; i < 8; i++) {
        size_t base = ((size_t)b*TT + t0 + ty*8 + i)*DD + o0 + tx*4;
        float4 v = make_float4(acc[i][0], acc[i][1], acc[i][2], acc[i][3]);
        *reinterpret_cast<float4*>(&g_ctxT[base]) = v;
        __nv_bfloat16 p0,p1,p2,q0,q1,q2;
        split3(v.x, p0, p1, p2); split3(v.y, q0, q1, q2);
        __nv_bfloat162 t;
        t.x = p0; t.y = q0; *reinterpret_cast<__nv_bfloat162*>(&g_ctxL[0][base]) = t;
        t.x = p1; t.y = q1; *reinterpret_cast<__nv_bfloat162*>(&g_ctxL[1][base]) = t;
        t.x = p2; t.y = q2; *reinterpret_cast<__nv_bfloat162*>(&g_ctxL[2][base]) = t;
        split3(v.z, p0, p1, p2); split3(v.w, q0, q1, q2);
        t.x = p0; t.y = q0; *reinterpret_cast<__nv_bfloat162*>(&g_ctxL[0][base + 2]) = t;
        t.x = p1; t.y = q1; *reinterpret_cast<__nv_bfloat162*>(&g_ctxL[1][base + 2]) = t;
        t.x = p2; t.y = q2; *reinterpret_cast<__nv_bfloat162*>(&g_ctxL[2][base + 2]) = t;
    }
}

// ---------------- fuse1: cur = PReLU(wf1 . [x | ctx], a1) --------------------------
__global__ void __launch_bounds__(256) k_fuse1(const float* __restrict__ x,
                                               const float* __restrict__ a_ptr)
{
    __shared__ float As[16][132];
    __shared__ float Bs[16][68];
    int b  = blockIdx.z;
    int t0 = blockIdx.y * 128;
    int o0 = blockIdx.x * 64;
    int tid = threadIdx.x;
    int tx = tid & 15, ty = tid >> 4;
    int aK = tid & 15, aT = tid >> 4;      // A loader: 16 k x 16 rows per pass, 8 passes
    int bo = tid & 63, bk = tid >> 6;
    const float* xb   = x      + ((size_t)b*TT + t0)*DD;
    const float* ctxb = g_ctxT + ((size_t)b*TT + t0)*DD;
    float acc[8][4] = {};
    for (int k0 = 0; k0 < 2*DD; k0 += 16) {
        if (k0 < DD) {
            int c = k0 + aK;
#pragma unroll
            for (int p = 0; p < 8; p++) {
                int tm = aT + p*16;
                As[aK][tm] = xb[(size_t)tm*DD + c];
            }
        } else {
            int c = k0 - DD + aK;
#pragma unroll
            for (int p = 0; p < 8; p++) {
                int tm = aT + p*16;
                As[aK][tm] = ctxb[(size_t)tm*DD + c];
            }
        }
#pragma unroll
        for (int p = 0; p < 4; p++) {
            int kk = bk + p*4;
            Bs[kk][bo] = g_wf1T[(size_t)(k0 + kk)*DD + o0 + bo];
        }
        __syncthreads();
#pragma unroll
        for (int kk = 0; kk < 16; kk++) {
            float4 a0 = *reinterpret_cast<const float4*>(&As[kk][ty*8]);
            float4 a1 = *reinterpret_cast<const float4*>(&As[kk][ty*8 + 4]);
            float4 bv = *reinterpret_cast<const float4*>(&Bs[kk][tx*4]);
            FMA32();
        }
        __syncthreads();
    }
    float a = *a_ptr;
#pragma unroll
    for (int i = 0; i < 8; i++) {
        float4 v;
        float r;
        r = acc[i][0]; v.x = (r >= 0.f) ? r : a*r;
        r = acc[i][1]; v.y = (r >= 0.f) ? r : a*r;
        r = acc[i][2]; v.z = (r >= 0.f) ? r : a*r;
        r = acc[i][3]; v.w = (r >= 0.f) ? r : a*r;
        size_t base = ((size_t)b*TT + t0 + ty*8 + i)*DD + o0 + tx*4;
        *reinterpret_cast<float4*>(&g_cur[base]) = v;
    }
}

// ---------------- dist: z[r][m] = 2*cur.E_m - |E_m|^2 ------------------------------
__global__ void __launch_bounds__(256) k_dist()
{
    __shared__ float As[16][132];
    __shared__ float Bs[16][68];
    int r0 = blockIdx.y * 128;
    int m0 = blockIdx.x * 64;
    int tid = threadIdx.x;
    int tx = tid & 15, ty = tid >> 4;
    int aK = tid & 15, aT = tid >> 4;
    int bo = tid & 63, bk = tid >> 6;
    float acc[8][4] = {};
    for (int k0 = 0; k0 < DD; k0 += 16) {
#pragma unroll
        for (int p = 0; p < 8; p++) {
            int rm = aT + p*16;
            As[aK][rm] = g_cur[(size_t)(r0 + rm)*DD + k0 + aK];
        }
#pragma unroll
        for (int p = 0; p < 4; p++) {
            int kk = bk + p*4;
            Bs[kk][bo] = g_ET[(size_t)(k0 + kk)*MM + m0 + bo];
        }
        __syncthreads();
#pragma unroll
        for (int kk = 0; kk < 16; kk++) {
            float4 a0 = *reinterpret_cast<const float4*>(&As[kk][ty*8]);
            float4 a1 = *reinterpret_cast<const float4*>(&As[kk][ty*8 + 4]);
            float4 bv = *reinterpret_cast<const float4*>(&Bs[kk][tx*4]);
            FMA32();
        }
        __syncthreads();
    }
    float e0 = g_e2[m0 + tx*4 + 0];
    float e1 = g_e2[m0 + tx*4 + 1];
    float e2v = g_e2[m0 + tx*4 + 2];
    float e3 = g_e2[m0 + tx*4 + 3];
#pragma unroll
    for (int i = 0; i < 8; i++) {
        float4 v;
        v.x = 2.0f*acc[i][0] - e0;
        v.y = 2.0f*acc[i][1] - e1;
        v.z = 2.0f*acc[i][2] - e2v;
        v.w = 2.0f*acc[i][3] - e3;
        *reinterpret_cast<float4*>(&g_z[(size_t)(r0 + ty*8 + i)*MM + m0 + tx*4]) = v;
    }
}

// ================= fuse2: HMMA bf16 3-limb (output-only, 1e-3 budget) ==============
#define AS_ELE (128*40)
#define BS_ELE (64*40)
#define MMA16816(C, A0,A1,A2,A3, B0,B1) \
    asm volatile("mma.sync.aligned.m16n8k16.row.col.f32.bf16.bf16.f32 " \
        "{%0,%1,%2,%3}, {%4,%5,%6,%7}, {%8,%9}, {%0,%1,%2,%3};" \
        : "+f"((C)[0]), "+f"((C)[1]), "+f"((C)[2]), "+f"((C)[3]) \
        : "r"(A0), "r"(A1), "r"(A2), "r"(A3), "r"(B0), "r"(B1))

__device__ __forceinline__ void mma_chunk3(const __nv_bfloat16* As, const __nv_bfloat16* Bs,
                                           float acc[2][4][4], int wm, int wn, int lane)
{
    const int PA[3] = {0,0,1};
    const int PB[3] = {0,1,0};
    int rq = lane >> 2;
    int kq = (lane & 3) * 2;
#pragma unroll
    for (int p = 0; p < 3; p++) {
        const __nv_bfloat16* A = As + PA[p]*AS_ELE + (wm*32 + rq)*40;
        const __nv_bfloat16* B = Bs + PB[p]*BS_ELE + (wn*32 + rq)*40;
#pragma unroll
        for (int kk = 0; kk < 32; kk += 16) {
            uint32_t bfr[4][2];
#pragma unroll
            for (int nt = 0; nt < 4; nt++) {
                bfr[nt][0] = *(const uint32_t*)(B + nt*8*40 + kk + kq);
                bfr[nt][1] = *(const uint32_t*)(B + nt*8*40 + kk + kq + 8);
            }
#pragma unroll
            for (int mt = 0; mt < 2; mt++) {
                const __nv_bfloat16* Am = A + mt*16*40;
                uint32_t a0 = *(const uint32_t*)(Am + kk + kq);
                uint32_t a1 = *(const uint32_t*)(Am + 8*40 + kk + kq);
                uint32_t a2 = *(const uint32_t*)(Am + kk + kq + 8);
                uint32_t a3 = *(const uint32_t*)(Am + 8*40 + kk + kq + 8);
#pragma unroll
                for (int nt = 0; nt < 4; nt++)
                    MMA16816(acc[mt][nt], a0, a1, a2, a3, bfr[nt][0], bfr[nt][1]);
            }
        }
    }
}

__global__ void __launch_bounds__(256, 2) k_fuse2_mma(const float* __restrict__ a_ptr,
                                                      float* __restrict__ outq)
{
    __shared__ __nv_bfloat16 As[2*AS_ELE + AS_ELE]; // limbs 0,1 used by A; slot2 spare
    __shared__ __nv_bfloat16 Bs[2*BS_ELE + BS_ELE];
    __shared__ int sIdx[128];
    int tid = threadIdx.x, lane = tid & 31, wid = tid >> 5;
    int wm = wid >> 1, wn = wid & 1;
    int o0 = blockIdx.x * 64, t0 = blockIdx.y * 128, b = blockIdx.z;
    size_t bt0 = (size_t)b*TT + t0;
    if (tid < 128) sIdx[tid] = g_idx[b*TT + t0 + tid];
    __syncthreads();
    float acc[2][4][4] = {};
    for (int ch = 0; ch < 16; ch++) {
        int k0 = (ch & 7) * 32;
        // A tile: limbs 0 and 1
#pragma unroll
        for (int q = 0; q < 8; q++) {
            int j = tid + 256*q;
            int row = j >> 4, c2 = (j & 15) * 2;
            size_t src;
            if (ch < 8) src = (size_t)sIdx[row]*DD + k0 + c2;
            else        src = (bt0 + row)*DD + k0 + c2;
            int d = row*40 + c2;
            const __nv_bfloat16* L0 = (ch < 8) ? g_EL[0] : g_ctxL[0];
            const __nv_bfloat16* L1 = (ch < 8) ? g_EL[1] : g_ctxL[1];
            *(uint32_t*)(As + 0*AS_ELE + d) = *(const uint32_t*)(L0 + src);
            *(uint32_t*)(As + 1*AS_ELE + d) = *(const uint32_t*)(L1 + src);
        }
        // B tile: wf2 limbs 0 and 1, k-col = ch*32
#pragma unroll
        for (int q = 0; q < 4; q++) {
            int j = tid + 256*q;
            int row = j >> 4, c2 = (j & 15) * 2;
            size_t src = (size_t)(o0 + row)*(2*DD) + ch*32 + c2;
            int d = row*40 + c2;
            *(uint32_t*)(Bs + 0*BS_ELE + d) = *(const uint32_t*)(g_wf2L[0] + src);
            *(uint32_t*)(Bs + 1*BS_ELE + d) = *(const uint32_t*)(g_wf2L[1] + src);
        }
        __syncthreads();
        mma_chunk3(As, Bs, acc, wm, wn, lane);
        __syncthreads();
    }
    float a = *a_ptr;
    int rq = lane >> 2, cq = (lane & 3) * 2;
#pragma unroll
    for (int mt = 0; mt < 2; mt++)
#pragma unroll
    for (int nt = 0; nt < 4; nt++) {
        int row = wm*32 + mt*16 + rq;
        int col = o0 + wn*32 + nt*8 + cq;
#pragma unroll
        for (int hh = 0; hh < 2; hh++) {
            float v0 = acc[mt][nt][hh*2 + 0];
            float v1 = acc[mt][nt][hh*2 + 1];
            v0 = (v0 >= 0.f) ? v0 : a*v0;
            v1 = (v1 >= 0.f) ? v1 : a*v1;
            size_t base = (bt0 + row + hh*8)*DD + col;
            *(float2*)(outq + base) = make_float2(v0, v1);
        }
    }
}

// ---------------- warp helpers (R6 verbatim) ---------------------------------------
__device__ __forceinline__ void wargmax(float& v, int& i)
{
#pragma unroll
    for (int off = 16; off; off >>= 1) {
        float ov = __shfl_down_sync(0xffffffffu, v, off);
        int   oi = __shfl_down_sync(0xffffffffu, i, off);
        if (ov > v || (ov == v && oi < i)) { v = ov; i = oi; }
    }
}
__device__ __forceinline__ float wsum(float v)
{
#pragma unroll
    for (int off = 16; off; off >>= 1) v += __shfl_down_sync(0xffffffffu, v, off);
    return v;
}

// ---------------- K4b: per-row argmax / softmax / gumbel (R6 verbatim) -------------
__global__ void __launch_bounds__(256) k_stats(const float* __restrict__ gu,
                                               float* __restrict__ out_inds,
                                               int write_inds)
{
    __shared__ float sV[8];  __shared__ int sI[8];
    __shared__ float sV2[8]; __shared__ int sI2[8];
    __shared__ float sS[8];
    __shared__ float sMax;   __shared__ int sHard;
    __shared__ float sSum;
    __shared__ int sHist[MM];
    int tid = threadIdx.x;
    int lane = tid & 31, w = tid >> 5;
#pragma unroll
    for (int q = 0; q < 4; q++) sHist[tid*4 + q] = 0;
    float acc0 = 0.f, acc1 = 0.f, acc2 = 0.f, acc3 = 0.f;
    int base = blockIdx.x * 128;
    __syncthreads();

    for (int r = 0; r < 128; r++) {
        size_t off = (size_t)(base + r)*MM + tid*4;
        float4 z = *reinterpret_cast<const float4*>(g_z + off);
        float4 u = *reinterpret_cast<const float4*>(gu + off);

        float hv = z.x; int hi = tid*4;
        if (z.y > hv) { hv = z.y; hi = tid*4 + 1; }
        if (z.z > hv) { hv = z.z; hi = tid*4 + 2; }
        if (z.w > hv) { hv = z.w; hi = tid*4 + 3; }

        const float lo = 1e-10f, hicl = 1.0f - 1e-7f;
        float y0 = z.x - logf(-logf(fminf(fmaxf(u.x, lo), hicl)));
        float y1 = z.y - logf(-logf(fminf(fmaxf(u.y, lo), hicl)));
        float y2 = z.z - logf(-logf(fminf(fmaxf(u.z, lo), hicl)));
        float y3 = z.w - logf(-logf(fminf(fmaxf(u.w, lo), hicl)));
        float yv = y0; int yi = tid*4;
        if (y1 > yv) { yv = y1; yi = tid*4 + 1; }
        if (y2 > yv) { yv = y2; yi = tid*4 + 2; }
        if (y3 > yv) { yv = y3; yi = tid*4 + 3; }

        float hvr = hv; int hir = hi;  wargmax(hvr, hir);
        float yvr = yv; int yir = yi;  wargmax(yvr, yir);
        if (lane == 0) { sV[w] = hvr; sI[w] = hir; sV2[w] = yvr; sI2[w] = yir; }
        __syncthreads();
        if (w == 0) {
            float v = (lane < 8) ? sV[lane] : -FLT_MAX;
            int   i = (lane < 8) ? sI[lane] : 0x7fffffff;
            wargmax(v, i);
            if (lane == 0) { sMax = v; sHard = i; }
        }
        if (w == 1) {
            float v = (lane < 8) ? sV2[lane] : -FLT_MAX;
            int   i = (lane < 8) ? sI2[lane] : 0x7fffffff;
            wargmax(v, i);
            if (lane == 0) {
                g_idx[base + r] = i;
                if (write_inds) out_inds[base + r] = (float)i;
            }
        }
        __syncthreads();
        if (tid == 0) sHist[sHard]++;
        float mx = sMax;
        float e0 = expf(z.x - mx);
        float e1 = expf(z.y - mx);
        float e2v = expf(z.z - mx);
        float e3 = expf(z.w - mx);
        float s = wsum(e0 + e1 + e2v + e3);
        if (lane == 0) sS[w] = s;
        __syncthreads();
        if (w == 0) {
            float v = (lane < 8) ? sS[lane] : 0.f;
            v = wsum(v);
            if (lane == 0) sSum = v;
        }
        __syncthreads();
        float inv = 1.0f / sSum;
        acc0 += e0*inv; acc1 += e1*inv; acc2 += e2v*inv; acc3 += e3*inv;
        __syncthreads();
    }
    float4 av = make_float4(acc0, acc1, acc2, acc3);
    *reinterpret_cast<float4*>(&g_avgp[blockIdx.x*MM + tid*4]) = av;
    int4 hv4 = make_int4(sHist[tid*4], sHist[tid*4+1], sHist[tid*4+2], sHist[tid*4+3]);
    *reinterpret_cast<int4*>(&g_hardp[blockIdx.x*MM + tid*4]) = hv4;
}

// ---------------- K5: entropy reductions (R6 verbatim) -----------------------------
__global__ void k_colred()
{
    int m = blockIdx.x;
    int tid = threadIdx.x;
    __shared__ float shf[256];
    __shared__ int   shi[256];
    shf[tid] = g_avgp[(size_t)tid*MM + m];
    shi[tid] = g_hardp[(size_t)tid*MM + m];
    __syncthreads();
    for (int st = 128; st; st >>= 1) {
        if (tid < st) { shf[tid] += shf[tid+st]; shi[tid] += shi[tid+st]; }
        __syncthreads();
    }
    if (tid == 0) {
        float ap = shf[0] / (float)NROWS;
        float hp = (float)shi[0] / (float)NROWS;
        g_terms[m]      = -ap * log2f(ap + 1e-10f);
        g_terms[MM + m] = -hp * log2f(hp + 1e-10f);
    }
}
__global__ void k_final(float* __restrict__ out, int write_ok)
{
    __shared__ float s1[256], s2[256];
    int tid = threadIdx.x;
    float a = 0.f, b = 0.f;
    for (int m = tid; m < MM; m += 256) { a += g_terms[m]; b += g_terms[MM + m]; }
    s1[tid] = a; s2[tid] = b; __syncthreads();
    for (int st = 128; st; st >>= 1) {
        if (tid < st) { s1[tid] += s1[tid+st]; s2[tid] += s2[tid+st]; }
        __syncthreads();
    }
    if (tid == 0 && write_ok) {
        out[QOUT + 0] = s2[0];   // code_perplexity (hard)
        out[QOUT + 1] = s1[0];   // prob_perplexity (soft)
    }
}

// ---------------- launch -----------------------------------------------------------
extern "C" void kernel_launch(void* const* d_in, const int* in_sizes, int n_in,
                              void* d_out, int out_size)
{
    const float* x     = (const float*)d_in[0];
    const float* noise = (const float*)d_in[1];
    const float* gu    = (const float*)d_in[2];
    const int*   epo   = (const int*)  d_in[3];
    const float* E     = (const float*)d_in[4];
    const float* wctx  = (const float*)d_in[5];
    const float* wf1   = (const float*)d_in[6];
    const float* a1    = (const float*)d_in[7];
    const float* wf2   = (const float*)d_in[8];
    const float* a2    = (const float*)d_in[9];
    float* out = (float*)d_out;
    int tail_ok = (out_size >= OUT_NEED) ? 1 : 0;

    k_scale<<<BB, 256>>>(x, epo);
    k_prep_w<<<(KC*DD + 255)/256, 256>>>(wctx, wf1);
    k_prep_E<<<(DD*MM)/256, 256>>>(E);
    k_prep_wf2<<<(DD*2*DD)/256, 256>>>(wf2);
    k_e2<<<MM/8, 256>>>(E);
    k_cn<<<dim3((TJ + 31)/32, DD/32, BB), dim3(32, 8)>>>(x, noise);

    k_conv <<<dim3(DD/64, TT/128, BB), 256>>>();
    k_fuse1<<<dim3(DD/64, TT/128, BB), 256>>>(x, a1);
    k_dist <<<dim3(MM/64, NROWS/128), 256>>>();

    k_stats<<<256, 256>>>(gu, out + QOUT + 2, tail_ok);
    k_colred<<<MM, 256>>>();
    k_final<<<1, 256>>>(out, tail_ok);

    k_fuse2_mma<<<dim3(DD/64, TT/128, BB), 256>>>(a2, out);
}

// round 12
// speedup vs baseline: 1.2507x; 1.1046x over previous
#include <cuda_runtime.h>
#include <cuda_bf16.h>
#include <math.h>
#include <float.h>
#include <stdint.h>

#define BB 8
#define TT 4096
#define DD 256
#define MM 1024
#define CTX 7
#define TJ 4102            // T-1+CTX
#define KC (DD*CTX)        // 1792
#define NROWS (BB*TT)      // 32768
#define QOUT (NROWS*DD)    // 8388608
#define OUT_NEED (QOUT + 2 + NROWS)
#define NSB 512            // stats blocks (64 rows each)

// ================= global scratch (static; no runtime allocation) ==================
__device__ float g_cn[BB*DD*TJ];              // noisy padded ctx input [b][d][j]
__device__ float g_ctxT[NROWS*DD];            // conv output fp32 [bt][o] (z path)
__device__ __nv_bfloat16 g_ctxL[3][NROWS*DD]; // conv output bf16 limbs (fuse2 only)
__device__ float g_cur[NROWS*DD];             // fuse1 output fp32 [bt][d]
__device__ float g_z[(size_t)NROWS*MM];       // z = 2*cur.E - |E|^2
__device__ float g_wT[KC*DD];                 // w_ctx transposed [k][o]
__device__ float g_wf1T[2*DD*DD];             // w_f1 transposed [c][o]
__device__ float g_ET[DD*MM];                 // E transposed [d][m]
__device__ __nv_bfloat16 g_EL[3][MM*DD];      // codebook bf16 limbs [m][d] (fuse2)
__device__ __nv_bfloat16 g_wf2L[3][DD*2*DD];  // wf2 bf16 limbs [o][c] (fuse2)
__device__ float g_e2[MM];
__device__ float g_coef[BB];
__device__ int   g_idx[NROWS];
__device__ float g_avgp[NSB*MM];
__device__ int   g_hardp[NSB*MM];
__device__ float g_terms[2*MM];

// Exact 3-limb bf16 split
__device__ __forceinline__ void split3(float v, __nv_bfloat16& l0, __nv_bfloat16& l1,
                                       __nv_bfloat16& l2)
{
    l0 = __float2bfloat16_rn(v);
    float r = v - __bfloat162float(l0);
    l1 = __float2bfloat16_rn(r);
    float r2 = r - __bfloat162float(l1);
    l2 = __float2bfloat16_rn(r2);
}

// ---------------- K0: batch RMS scale + epo decode ---------------------------------
__global__ void k_scale(const float* __restrict__ x, const int* __restrict__ epo_raw)
{
    int b = blockIdx.x;
    const float* xb = x + (size_t)b*TT*DD;
    const int N = (TT-1)*DD;
    double s = 0.0;
    for (int i = threadIdx.x; i < N; i += 256) { float v = xb[i]; s += (double)v*v; }
    __shared__ double sh[256];
    sh[threadIdx.x] = s; __syncthreads();
    for (int st = 128; st; st >>= 1) {
        if (threadIdx.x < st) sh[threadIdx.x] += sh[threadIdx.x+st];
        __syncthreads();
    }
    if (threadIdx.x == 0) {
        int w = epo_raw[0];
        float epo = (w >= 0 && w < 1000000) ? (float)w : __int_as_float(w);
        float scale = sqrtf((float)(sh[0] / ((double)DD * (double)TJ)));
        g_coef[b] = 0.5f * scale * powf(0.5f, epo * 0.1f);
    }
}

// ---------------- K1: noisy padded ctx input [b][d][j] -----------------------------
__global__ void k_cn(const float* __restrict__ x, const float* __restrict__ noise)
{
    __shared__ float tile[32][33];
    int b  = blockIdx.z;
    int j0 = blockIdx.x * 32;
    int d0 = blockIdx.y * 32;
    int tx = threadIdx.x, ty = threadIdx.y;      // (32, 8)
    int t0 = j0 - CTX;
    const float* xb = x + (size_t)b*TT*DD;
#pragma unroll
    for (int r = 0; r < 4; r++) {
        int t = t0 + ty + r*8;
        tile[ty + r*8][tx] = (t >= 0 && t < TT-1) ? xb[(size_t)t*DD + d0 + tx] : 0.0f;
    }
    __syncthreads();
    float coef = g_coef[b];
    const float* nb = noise + (size_t)b*DD*TJ;
    float*       cb = g_cn  + (size_t)b*DD*TJ;
    int j = j0 + tx;
    if (j < TJ) {
#pragma unroll
        for (int r = 0; r < 4; r++) {
            int d = d0 + ty + r*8;
            cb[(size_t)d*TJ + j] = tile[tx][ty + r*8] + coef * nb[(size_t)d*TJ + j];
        }
    }
}

// ---------------- weight / codebook prep -------------------------------------------
__global__ void k_prep_w(const float* __restrict__ wctx, const float* __restrict__ wf1)
{
    int i = blockIdx.x * 256 + threadIdx.x;
    if (i < KC*DD) {
        int k = i / DD, o = i - k*DD;
        g_wT[i] = wctx[(size_t)o*KC + k];
    }
    if (i < 2*DD*DD) {
        int c = i / DD, o = i - c*DD;
        g_wf1T[i] = wf1[(size_t)o*(2*DD) + c];
    }
}
__global__ void k_prep_E(const float* __restrict__ E)
{
    int i = blockIdx.x * 256 + threadIdx.x;
    if (i < DD*MM) {
        int d = i / MM, m = i - d*MM;
        g_ET[i] = E[(size_t)m*DD + d];
        __nv_bfloat16 l0, l1, l2; split3(E[i], l0, l1, l2);
        g_EL[0][i] = l0; g_EL[1][i] = l1; g_EL[2][i] = l2;
    }
}
__global__ void k_prep_wf2(const float* __restrict__ wf2)
{
    int i = blockIdx.x * 256 + threadIdx.x;
    if (i < DD*2*DD) {
        __nv_bfloat16 l0, l1, l2; split3(wf2[i], l0, l1, l2);
        g_wf2L[0][i] = l0; g_wf2L[1][i] = l1; g_wf2L[2][i] = l2;
    }
}
__global__ void k_e2(const float* __restrict__ E)
{
    int lane = threadIdx.x & 31, w = threadIdx.x >> 5;
    int m = blockIdx.x * 8 + w;
    const float* row = E + (size_t)m*DD;
    double s = 0.0;
    for (int k = lane; k < DD; k += 32) { float v = row[k]; s += (double)v*v; }
#pragma unroll
    for (int off = 16; off; off >>= 1) s += __shfl_down_sync(0xffffffffu, s, off);
    if (lane == 0) g_e2[m] = (float)s;
}

// ================= fp32 FFMA GEMMs, double-buffered (k-order == R9/R6) =============
#define FMA32() do { \
    acc[0][0] += a0.x*bv.x; acc[0][1] += a0.x*bv.y; acc[0][2] += a0.x*bv.z; acc[0][3] += a0.x*bv.w; \
    acc[1][0] += a0.y*bv.x; acc[1][1] += a0.y*bv.y; acc[1][2] += a0.y*bv.z; acc[1][3] += a0.y*bv.w; \
    acc[2][0] += a0.z*bv.x; acc[2][1] += a0.z*bv.y; acc[2][2] += a0.z*bv.z; acc[2][3] += a0.z*bv.w; \
    acc[3][0] += a0.w*bv.x; acc[3][1] += a0.w*bv.y; acc[3][2] += a0.w*bv.z; acc[3][3] += a0.w*bv.w; \
    acc[4][0] += a1.x*bv.x; acc[4][1] += a1.x*bv.y; acc[4][2] += a1.x*bv.z; acc[4][3] += a1.x*bv.w; \
    acc[5][0] += a1.y*bv.x; acc[5][1] += a1.y*bv.y; acc[5][2] += a1.y*bv.z; acc[5][3] += a1.y*bv.w; \
    acc[6][0] += a1.z*bv.x; acc[6][1] += a1.z*bv.y; acc[6][2] += a1.z*bv.z; acc[6][3] += a1.z*bv.w; \
    acc[7][0] += a1.w*bv.x; acc[7][1] += a1.w*bv.y; acc[7][2] += a1.w*bv.z; acc[7][3] += a1.w*bv.w; } while(0)

// ---------------- conv: ctx[bt][o] = sum_k cn[t + k%7][k/7] * wT[k][o] -------------
__global__ void __launch_bounds__(256) k_conv()
{
    __shared__ float As[2][16][132];
    __shared__ float Bs[2][16][68];
    int b  = blockIdx.z;
    int t0 = blockIdx.y * 128;
    int o0 = blockIdx.x * 64;
    int tid = threadIdx.x;
    int tx = tid & 15, ty = tid >> 4;
    int lt = tid & 127, lk = tid >> 7;
    int bo = tid & 63,  bk = tid >> 6;
    const float* cnb = g_cn + (size_t)b*DD*TJ;
    float acc[8][4] = {};
    float pa[8], pb[4];
#pragma unroll
    for (int p = 0; p < 8; p++) {
        int k = lk + p*2;
        int i = k / 7, h = k - i*7;
        pa[p] = cnb[(size_t)i*TJ + t0 + lt + h];
    }
#pragma unroll
    for (int p = 0; p < 4; p++)
        pb[p] = g_wT[(size_t)(bk + p*4)*DD + o0 + bo];
    const int NIT = KC/16;
    for (int it = 0; it < NIT; it++) {
        int buf = it & 1;
#pragma unroll
        for (int p = 0; p < 8; p++) As[buf][lk + p*2][lt] = pa[p];
#pragma unroll
        for (int p = 0; p < 4; p++) Bs[buf][bk + p*4][bo] = pb[p];
        __syncthreads();
        if (it + 1 < NIT) {
            int k0 = (it+1)*16;
#pragma unroll
            for (int p = 0; p < 8; p++) {
                int k = k0 + lk + p*2;
                int i = k / 7, h = k - i*7;
                pa[p] = cnb[(size_t)i*TJ + t0 + lt + h];
            }
#pragma unroll
            for (int p = 0; p < 4; p++)
                pb[p] = g_wT[(size_t)(k0 + bk + p*4)*DD + o0 + bo];
        }
#pragma unroll
        for (int kk = 0; kk < 16; kk++) {
            float4 a0 = *reinterpret_cast<const float4*>(&As[buf][kk][ty*8]);
            float4 a1 = *reinterpret_cast<const float4*>(&As[buf][kk][ty*8 + 4]);
            float4 bv = *reinterpret_cast<const float4*>(&Bs[buf][kk][tx*4]);
            FMA32();
        }
    }
#pragma unroll
    for (int i = 0; i < 8; i++) {
        size_t base = ((size_t)b*TT + t0 + ty*8 + i)*DD + o0 + tx*4;
        float4 v = make_float4(acc[i][0], acc[i][1], acc[i][2], acc[i][3]);
        *reinterpret_cast<float4*>(&g_ctxT[base]) = v;
        __nv_bfloat16 p0,p1,p2,q0,q1,q2;
        split3(v.x, p0, p1, p2); split3(v.y, q0, q1, q2);
        __nv_bfloat162 t;
        t.x = p0; t.y = q0; *reinterpret_cast<__nv_bfloat162*>(&g_ctxL[0][base]) = t;
        t.x = p1; t.y = q1; *reinterpret_cast<__nv_bfloat162*>(&g_ctxL[1][base]) = t;
        t.x = p2; t.y = q2; *reinterpret_cast<__nv_bfloat162*>(&g_ctxL[2][base]) = t;
        split3(v.z, p0, p1, p2); split3(v.w, q0, q1, q2);
        t.x = p0; t.y = q0; *reinterpret_cast<__nv_bfloat162*>(&g_ctxL[0][base + 2]) = t;
        t.x = p1; t.y = q1; *reinterpret_cast<__nv_bfloat162*>(&g_ctxL[1][base + 2]) = t;
        t.x = p2; t.y = q2; *reinterpret_cast<__nv_bfloat162*>(&g_ctxL[2][base + 2]) = t;
    }
}

// ---------------- fuse1: cur = PReLU(wf1 . [x | ctx], a1) --------------------------
__global__ void __launch_bounds__(256) k_fuse1(const float* __restrict__ x,
                                               const float* __restrict__ a_ptr)
{
    __shared__ float As[2][16][132];
    __shared__ float Bs[2][16][68];
    int b  = blockIdx.z;
    int t0 = blockIdx.y * 128;
    int o0 = blockIdx.x * 64;
    int tid = threadIdx.x;
    int tx = tid & 15, ty = tid >> 4;
    int aK = tid & 15, aT = tid >> 4;
    int bo = tid & 63, bk = tid >> 6;
    const float* xb   = x      + ((size_t)b*TT + t0)*DD;
    const float* ctxb = g_ctxT + ((size_t)b*TT + t0)*DD;
    float acc[8][4] = {};
    float pa[8], pb[4];
#pragma unroll
    for (int p = 0; p < 8; p++)
        pa[p] = xb[(size_t)(aT + p*16)*DD + aK];
#pragma unroll
    for (int p = 0; p < 4; p++)
        pb[p] = g_wf1T[(size_t)(bk + p*4)*DD + o0 + bo];
    const int NIT = (2*DD)/16;
    for (int it = 0; it < NIT; it++) {
        int buf = it & 1;
#pragma unroll
        for (int p = 0; p < 8; p++) As[buf][aK][aT + p*16] = pa[p];
#pragma unroll
        for (int p = 0; p < 4; p++) Bs[buf][bk + p*4][bo] = pb[p];
        __syncthreads();
        if (it + 1 < NIT) {
            int k0 = (it+1)*16;
            const float* src = (k0 < DD) ? xb : ctxb;
            int c = ((k0 < DD) ? k0 : k0 - DD) + aK;
#pragma unroll
            for (int p = 0; p < 8; p++)
                pa[p] = src[(size_t)(aT + p*16)*DD + c];
#pragma unroll
            for (int p = 0; p < 4; p++)
                pb[p] = g_wf1T[(size_t)(k0 + bk + p*4)*DD + o0 + bo];
        }
#pragma unroll
        for (int kk = 0; kk < 16; kk++) {
            float4 a0 = *reinterpret_cast<const float4*>(&As[buf][kk][ty*8]);
            float4 a1 = *reinterpret_cast<const float4*>(&As[buf][kk][ty*8 + 4]);
            float4 bv = *reinterpret_cast<const float4*>(&Bs[buf][kk][tx*4]);
            FMA32();
        }
    }
    float a = *a_ptr;
#pragma unroll
    for (int i = 0; i < 8; i++) {
        float4 v;
        float r;
        r = acc[i][0]; v.x = (r >= 0.f) ? r : a*r;
        r = acc[i][1]; v.y = (r >= 0.f) ? r : a*r;
        r = acc[i][2]; v.z = (r >= 0.f) ? r : a*r;
        r = acc[i][3]; v.w = (r >= 0.f) ? r : a*r;
        size_t base = ((size_t)b*TT + t0 + ty*8 + i)*DD + o0 + tx*4;
        *reinterpret_cast<float4*>(&g_cur[base]) = v;
    }
}

// ---------------- dist: z[r][m] = 2*cur.E_m - |E_m|^2 ------------------------------
__global__ void __launch_bounds__(256) k_dist()
{
    __shared__ float As[2][16][132];
    __shared__ float Bs[2][16][68];
    int r0 = blockIdx.y * 128;
    int m0 = blockIdx.x * 64;
    int tid = threadIdx.x;
    int tx = tid & 15, ty = tid >> 4;
    int aK = tid & 15, aT = tid >> 4;
    int bo = tid & 63, bk = tid >> 6;
    float acc[8][4] = {};
    float pa[8], pb[4];
#pragma unroll
    for (int p = 0; p < 8; p++)
        pa[p] = g_cur[(size_t)(r0 + aT + p*16)*DD + aK];
#pragma unroll
    for (int p = 0; p < 4; p++)
        pb[p] = g_ET[(size_t)(bk + p*4)*MM + m0 + bo];
    const int NIT = DD/16;
    for (int it = 0; it < NIT; it++) {
        int buf = it & 1;
#pragma unroll
        for (int p = 0; p < 8; p++) As[buf][aK][aT + p*16] = pa[p];
#pragma unroll
        for (int p = 0; p < 4; p++) Bs[buf][bk + p*4][bo] = pb[p];
        __syncthreads();
        if (it + 1 < NIT) {
            int k0 = (it+1)*16;
#pragma unroll
            for (int p = 0; p < 8; p++)
                pa[p] = g_cur[(size_t)(r0 + aT + p*16)*DD + k0 + aK];
#pragma unroll
            for (int p = 0; p < 4; p++)
                pb[p] = g_ET[(size_t)(k0 + bk + p*4)*MM + m0 + bo];
        }
#pragma unroll
        for (int kk = 0; kk < 16; kk++) {
            float4 a0 = *reinterpret_cast<const float4*>(&As[buf][kk][ty*8]);
            float4 a1 = *reinterpret_cast<const float4*>(&As[buf][kk][ty*8 + 4]);
            float4 bv = *reinterpret_cast<const float4*>(&Bs[buf][kk][tx*4]);
            FMA32();
        }
    }
    float e0 = g_e2[m0 + tx*4 + 0];
    float e1 = g_e2[m0 + tx*4 + 1];
    float e2v = g_e2[m0 + tx*4 + 2];
    float e3 = g_e2[m0 + tx*4 + 3];
#pragma unroll
    for (int i = 0; i < 8; i++) {
        float4 v;
        v.x = 2.0f*acc[i][0] - e0;
        v.y = 2.0f*acc[i][1] - e1;
        v.z = 2.0f*acc[i][2] - e2v;
        v.w = 2.0f*acc[i][3] - e3;
        *reinterpret_cast<float4*>(&g_z[(size_t)(r0 + ty*8 + i)*MM + m0 + tx*4]) = v;
    }
}

// ================= fuse2: HMMA bf16 limbs (output-only, 1e-3 budget) ===============
#define AS_ELE (128*40)
#define BS_ELE (64*40)
#define MMA16816(C, A0,A1,A2,A3, B0,B1) \
    asm volatile("mma.sync.aligned.m16n8k16.row.col.f32.bf16.bf16.f32 " \
        "{%0,%1,%2,%3}, {%4,%5,%6,%7}, {%8,%9}, {%0,%1,%2,%3};" \
        : "+f"((C)[0]), "+f"((C)[1]), "+f"((C)[2]), "+f"((C)[3]) \
        : "r"(A0), "r"(A1), "r"(A2), "r"(A3), "r"(B0), "r"(B1))

__device__ __forceinline__ void mma_chunk3(const __nv_bfloat16* As, const __nv_bfloat16* Bs,
                                           float acc[2][4][4], int wm, int wn, int lane)
{
    const int PA[3] = {0,0,1};
    const int PB[3] = {0,1,0};
    int rq = lane >> 2;
    int kq = (lane & 3) * 2;
#pragma unroll
    for (int p = 0; p < 3; p++) {
        const __nv_bfloat16* A = As + PA[p]*AS_ELE + (wm*32 + rq)*40;
        const __nv_bfloat16* B = Bs + PB[p]*BS_ELE + (wn*32 + rq)*40;
#pragma unroll
        for (int kk = 0; kk < 32; kk += 16) {
            uint32_t bfr[4][2];
#pragma unroll
            for (int nt = 0; nt < 4; nt++) {
                bfr[nt][0] = *(const uint32_t*)(B + nt*8*40 + kk + kq);
                bfr[nt][1] = *(const uint32_t*)(B + nt*8*40 + kk + kq + 8);
            }
#pragma unroll
            for (int mt = 0; mt < 2; mt++) {
                const __nv_bfloat16* Am = A + mt*16*40;
                uint32_t a0 = *(const uint32_t*)(Am + kk + kq);
                uint32_t a1 = *(const uint32_t*)(Am + 8*40 + kk + kq);
                uint32_t a2 = *(const uint32_t*)(Am + kk + kq + 8);
                uint32_t a3 = *(const uint32_t*)(Am + 8*40 + kk + kq + 8);
#pragma unroll
                for (int nt = 0; nt < 4; nt++)
                    MMA16816(acc[mt][nt], a0, a1, a2, a3, bfr[nt][0], bfr[nt][1]);
            }
        }
    }
}

__global__ void __launch_bounds__(256, 2) k_fuse2_mma(const float* __restrict__ a_ptr,
                                                      float* __restrict__ outq)
{
    __shared__ __nv_bfloat16 As[2*AS_ELE];
    __shared__ __nv_bfloat16 Bs[2*BS_ELE];
    __shared__ int sIdx[128];
    int tid = threadIdx.x, lane = tid & 31, wid = tid >> 5;
    int wm = wid >> 1, wn = wid & 1;
    int o0 = blockIdx.x * 64, t0 = blockIdx.y * 128, b = blockIdx.z;
    size_t bt0 = (size_t)b*TT + t0;
    if (tid < 128) sIdx[tid] = g_idx[b*TT + t0 + tid];
    __syncthreads();
    float acc[2][4][4] = {};
    for (int ch = 0; ch < 16; ch++) {
        int k0 = (ch & 7) * 32;
#pragma unroll
        for (int q = 0; q < 8; q++) {
            int j = tid + 256*q;
            int row = j >> 4, c2 = (j & 15) * 2;
            size_t src;
            if (ch < 8) src = (size_t)sIdx[row]*DD + k0 + c2;
            else        src = (bt0 + row)*DD + k0 + c2;
            int d = row*40 + c2;
            const __nv_bfloat16* L0 = (ch < 8) ? g_EL[0] : g_ctxL[0];
            const __nv_bfloat16* L1 = (ch < 8) ? g_EL[1] : g_ctxL[1];
            *(uint32_t*)(As + 0*AS_ELE + d) = *(const uint32_t*)(L0 + src);
            *(uint32_t*)(As + 1*AS_ELE + d) = *(const uint32_t*)(L1 + src);
        }
#pragma unroll
        for (int q = 0; q < 4; q++) {
            int j = tid + 256*q;
            int row = j >> 4, c2 = (j & 15) * 2;
            size_t src = (size_t)(o0 + row)*(2*DD) + ch*32 + c2;
            int d = row*40 + c2;
            *(uint32_t*)(Bs + 0*BS_ELE + d) = *(const uint32_t*)(g_wf2L[0] + src);
            *(uint32_t*)(Bs + 1*BS_ELE + d) = *(const uint32_t*)(g_wf2L[1] + src);
        }
        __syncthreads();
        mma_chunk3(As, Bs, acc, wm, wn, lane);
        __syncthreads();
    }
    float a = *a_ptr;
    int rq = lane >> 2, cq = (lane & 3) * 2;
#pragma unroll
    for (int mt = 0; mt < 2; mt++)
#pragma unroll
    for (int nt = 0; nt < 4; nt++) {
        int row = wm*32 + mt*16 + rq;
        int col = o0 + wn*32 + nt*8 + cq;
#pragma unroll
        for (int hh = 0; hh < 2; hh++) {
            float v0 = acc[mt][nt][hh*2 + 0];
            float v1 = acc[mt][nt][hh*2 + 1];
            v0 = (v0 >= 0.f) ? v0 : a*v0;
            v1 = (v1 >= 0.f) ? v1 : a*v1;
            size_t base = (bt0 + row + hh*8)*DD + col;
            *(float2*)(outq + base) = make_float2(v0, v1);
        }
    }
}

// ---------------- warp helpers -----------------------------------------------------
__device__ __forceinline__ void wargmax(float& v, int& i)
{
#pragma unroll
    for (int off = 16; off; off >>= 1) {
        float ov = __shfl_down_sync(0xffffffffu, v, off);
        int   oi = __shfl_down_sync(0xffffffffu, i, off);
        if (ov > v || (ov == v && oi < i)) { v = ov; i = oi; }
    }
}
__device__ __forceinline__ float wsum(float v)
{
#pragma unroll
    for (int off = 16; off; off >>= 1) v += __shfl_down_sync(0xffffffffu, v, off);
    return v;
}

// ---------------- K4b: per-row argmax / softmax / gumbel ---------------------------
// g = -log(-log u): inner log accurate (u->1 amplification), outer via __logf
__global__ void __launch_bounds__(256) k_stats(const float* __restrict__ gu,
                                               float* __restrict__ out_inds,
                                               int write_inds)
{
    __shared__ float sV[8];  __shared__ int sI[8];
    __shared__ float sV2[8]; __shared__ int sI2[8];
    __shared__ float sS[8];
    __shared__ float sMax;   __shared__ int sHard;
    __shared__ float sSum;
    __shared__ int sHist[MM];
    int tid = threadIdx.x;
    int lane = tid & 31, w = tid >> 5;
#pragma unroll
    for (int q = 0; q < 4; q++) sHist[tid*4 + q] = 0;
    float acc0 = 0.f, acc1 = 0.f, acc2 = 0.f, acc3 = 0.f;
    int base = blockIdx.x * 64;
    __syncthreads();

    for (int r = 0; r < 64; r++) {
        size_t off = (size_t)(base + r)*MM + tid*4;
        float4 z = *reinterpret_cast<const float4*>(g_z + off);
        float4 u = *reinterpret_cast<const float4*>(gu + off);

        float hv = z.x; int hi = tid*4;
        if (z.y > hv) { hv = z.y; hi = tid*4 + 1; }
        if (z.z > hv) { hv = z.z; hi = tid*4 + 2; }
        if (z.w > hv) { hv = z.w; hi = tid*4 + 3; }

        const float lo = 1e-10f, hicl = 1.0f - 1e-7f;
        float y0 = z.x - __logf(-logf(fminf(fmaxf(u.x, lo), hicl)));
        float y1 = z.y - __logf(-logf(fminf(fmaxf(u.y, lo), hicl)));
        float y2 = z.z - __logf(-logf(fminf(fmaxf(u.z, lo), hicl)));
        float y3 = z.w - __logf(-logf(fminf(fmaxf(u.w, lo), hicl)));
        float yv = y0; int yi = tid*4;
        if (y1 > yv) { yv = y1; yi = tid*4 + 1; }
        if (y2 > yv) { yv = y2; yi = tid*4 + 2; }
        if (y3 > yv) { yv = y3; yi = tid*4 + 3; }

        float hvr = hv; int hir = hi;  wargmax(hvr, hir);
        float yvr = yv; int yir = yi;  wargmax(yvr, yir);
        if (lane == 0) { sV[w] = hvr; sI[w] = hir; sV2[w] = yvr; sI2[w] = yir; }
        __syncthreads();
        if (w == 0) {
            float v = (lane < 8) ? sV[lane] : -FLT_MAX;
            int   i = (lane < 8) ? sI[lane] : 0x7fffffff;
            wargmax(v, i);
            if (lane == 0) { sMax = v; sHard = i; }
        }
        if (w == 1) {
            float v = (lane < 8) ? sV2[lane] : -FLT_MAX;
            int   i = (lane < 8) ? sI2[lane] : 0x7fffffff;
            wargmax(v, i);
            if (lane == 0) {
                g_idx[base + r] = i;
                if (write_inds) out_inds[base + r] = (float)i;
            }
        }
        __syncthreads();
        if (tid == 0) sHist[sHard]++;
        float mx = sMax;
        float e0 = __expf(z.x - mx);
        float e1 = __expf(z.y - mx);
        float e2v = __expf(z.z - mx);
        float e3 = __expf(z.w - mx);
        float s = wsum(e0 + e1 + e2v + e3);
        if (lane == 0) sS[w] = s;
        __syncthreads();
        if (w == 0) {
            float v = (lane < 8) ? sS[lane] : 0.f;
            v = wsum(v);
            if (lane == 0) sSum = v;
        }
        __syncthreads();
        float inv = 1.0f / sSum;
        acc0 += e0*inv; acc1 += e1*inv; acc2 += e2v*inv; acc3 += e3*inv;
        __syncthreads();
    }
    float4 av = make_float4(acc0, acc1, acc2, acc3);
    *reinterpret_cast<float4*>(&g_avgp[(size_t)blockIdx.x*MM + tid*4]) = av;
    int4 hv4 = make_int4(sHist[tid*4], sHist[tid*4+1], sHist[tid*4+2], sHist[tid*4+3]);
    *reinterpret_cast<int4*>(&g_hardp[(size_t)blockIdx.x*MM + tid*4]) = hv4;
}

// ---------------- K5: entropy reductions -------------------------------------------
__global__ void k_colred()
{
    int m = blockIdx.x;
    int tid = threadIdx.x;
    __shared__ float shf[256];
    __shared__ int   shi[256];
    shf[tid] = g_avgp[(size_t)tid*MM + m] + g_avgp[(size_t)(tid + 256)*MM + m];
    shi[tid] = g_hardp[(size_t)tid*MM + m] + g_hardp[(size_t)(tid + 256)*MM + m];
    __syncthreads();
    for (int st = 128; st; st >>= 1) {
        if (tid < st) { shf[tid] += shf[tid+st]; shi[tid] += shi[tid+st]; }
        __syncthreads();
    }
    if (tid == 0) {
        float ap = shf[0] / (float)NROWS;
        float hp = (float)shi[0] / (float)NROWS;
        g_terms[m]      = -ap * log2f(ap + 1e-10f);
        g_terms[MM + m] = -hp * log2f(hp + 1e-10f);
    }
}
__global__ void k_final(float* __restrict__ out, int write_ok)
{
    __shared__ float s1[256], s2[256];
    int tid = threadIdx.x;
    float a = 0.f, b = 0.f;
    for (int m = tid; m < MM; m += 256) { a += g_terms[m]; b += g_terms[MM + m]; }
    s1[tid] = a; s2[tid] = b; __syncthreads();
    for (int st = 128; st; st >>= 1) {
        if (tid < st) { s1[tid] += s1[tid+st]; s2[tid] += s2[tid+st]; }
        __syncthreads();
    }
    if (tid == 0 && write_ok) {
        out[QOUT + 0] = s2[0];   // code_perplexity (hard)
        out[QOUT + 1] = s1[0];   // prob_perplexity (soft)
    }
}

// ---------------- launch (k_conv at slot 4 for ncu capture) ------------------------
extern "C" void kernel_launch(void* const* d_in, const int* in_sizes, int n_in,
                              void* d_out, int out_size)
{
    const float* x     = (const float*)d_in[0];
    const float* noise = (const float*)d_in[1];
    const float* gu    = (const float*)d_in[2];
    const int*   epo   = (const int*)  d_in[3];
    const float* E     = (const float*)d_in[4];
    const float* wctx  = (const float*)d_in[5];
    const float* wf1   = (const float*)d_in[6];
    const float* a1    = (const float*)d_in[7];
    const float* wf2   = (const float*)d_in[8];
    const float* a2    = (const float*)d_in[9];
    float* out = (float*)d_out;
    int tail_ok = (out_size >= OUT_NEED) ? 1 : 0;

    k_scale<<<BB, 256>>>(x, epo);                               // 1
    k_prep_w<<<(KC*DD + 255)/256, 256>>>(wctx, wf1);            // 2
    k_cn<<<dim3((TJ + 31)/32, DD/32, BB), dim3(32, 8)>>>(x, noise); // 3
    k_conv <<<dim3(DD/64, TT/128, BB), 256>>>();                // 4 <- ncu capture slot
    k_prep_E<<<(DD*MM)/256, 256>>>(E);                          // 5
    k_e2<<<MM/8, 256>>>(E);                                     // 6
    k_fuse1<<<dim3(DD/64, TT/128, BB), 256>>>(x, a1);           // 7
    k_dist <<<dim3(MM/64, NROWS/128), 256>>>();                 // 8
    k_prep_wf2<<<(DD*2*DD)/256, 256>>>(wf2);                    // 9
    k_stats<<<NSB, 256>>>(gu, out + QOUT + 2, tail_ok);         // 10
    k_colred<<<MM, 256>>>();                                    // 11
    k_final<<<1, 256>>>(out, tail_ok);                          // 12
    k_fuse2_mma<<<dim3(DD/64, TT/128, BB), 256>>>(a2, out);     // 13
}

// round 13
// speedup vs baseline: 1.3096x; 1.0471x over previous
#include <cuda_runtime.h>
#include <cuda_bf16.h>
#include <math.h>
#include <float.h>
#include <stdint.h>

#define BB 8
#define TT 4096
#define DD 256
#define MM 1024
#define CTX 7
#define TJ 4102            // T-1+CTX
#define KC (DD*CTX)        // 1792
#define NROWS (BB*TT)      // 32768
#define QOUT (NROWS*DD)    // 8388608
#define OUT_NEED (QOUT + 2 + NROWS)
#define NSB 512            // stats blocks (64 rows each)

// ================= global scratch (static; no runtime allocation) ==================
__device__ float g_cn[BB*DD*TJ];              // noisy padded ctx input [b][d][j]
__device__ float g_ctxT[NROWS*DD];            // conv output fp32 [bt][o] (z path)
__device__ __nv_bfloat16 g_ctxL[3][NROWS*DD]; // conv output bf16 limbs (fuse2 only)
__device__ float g_cur[NROWS*DD];             // fuse1 output fp32 [bt][d]
__device__ float g_z[(size_t)NROWS*MM];       // z = 2*cur.E - |E|^2
__device__ float g_wT[KC*DD];                 // w_ctx transposed [k][o]
__device__ float g_wf1T[2*DD*DD];             // w_f1 transposed [c][o]
__device__ float g_ET[DD*MM];                 // E transposed [d][m]
__device__ __nv_bfloat16 g_EL[3][MM*DD];      // codebook bf16 limbs [m][d] (fuse2)
__device__ __nv_bfloat16 g_wf2L[3][DD*2*DD];  // wf2 bf16 limbs [o][c] (fuse2)
__device__ float g_e2[MM];
__device__ float g_coef[BB];
__device__ int   g_idx[NROWS];
__device__ float g_avgp[NSB*MM];
__device__ int   g_hardp[NSB*MM];
__device__ float g_terms[2*MM];

// Exact 3-limb bf16 split
__device__ __forceinline__ void split3(float v, __nv_bfloat16& l0, __nv_bfloat16& l1,
                                       __nv_bfloat16& l2)
{
    l0 = __float2bfloat16_rn(v);
    float r = v - __bfloat162float(l0);
    l1 = __float2bfloat16_rn(r);
    float r2 = r - __bfloat162float(l1);
    l2 = __float2bfloat16_rn(r2);
}

// ---------------- K0: batch RMS scale + epo decode ---------------------------------
__global__ void k_scale(const float* __restrict__ x, const int* __restrict__ epo_raw)
{
    int b = blockIdx.x;
    const float* xb = x + (size_t)b*TT*DD;
    const int N = (TT-1)*DD;
    double s = 0.0;
    for (int i = threadIdx.x; i < N; i += 256) { float v = xb[i]; s += (double)v*v; }
    __shared__ double sh[256];
    sh[threadIdx.x] = s; __syncthreads();
    for (int st = 128; st; st >>= 1) {
        if (threadIdx.x < st) sh[threadIdx.x] += sh[threadIdx.x+st];
        __syncthreads();
    }
    if (threadIdx.x == 0) {
        int w = epo_raw[0];
        float epo = (w >= 0 && w < 1000000) ? (float)w : __int_as_float(w);
        float scale = sqrtf((float)(sh[0] / ((double)DD * (double)TJ)));
        g_coef[b] = 0.5f * scale * powf(0.5f, epo * 0.1f);
    }
}

// ---------------- K1: noisy padded ctx input [b][d][j] -----------------------------
__global__ void k_cn(const float* __restrict__ x, const float* __restrict__ noise)
{
    __shared__ float tile[32][33];
    int b  = blockIdx.z;
    int j0 = blockIdx.x * 32;
    int d0 = blockIdx.y * 32;
    int tx = threadIdx.x, ty = threadIdx.y;      // (32, 8)
    int t0 = j0 - CTX;
    const float* xb = x + (size_t)b*TT*DD;
#pragma unroll
    for (int r = 0; r < 4; r++) {
        int t = t0 + ty + r*8;
        tile[ty + r*8][tx] = (t >= 0 && t < TT-1) ? xb[(size_t)t*DD + d0 + tx] : 0.0f;
    }
    __syncthreads();
    float coef = g_coef[b];
    const float* nb = noise + (size_t)b*DD*TJ;
    float*       cb = g_cn  + (size_t)b*DD*TJ;
    int j = j0 + tx;
    if (j < TJ) {
#pragma unroll
        for (int r = 0; r < 4; r++) {
            int d = d0 + ty + r*8;
            cb[(size_t)d*TJ + j] = tile[tx][ty + r*8] + coef * nb[(size_t)d*TJ + j];
        }
    }
}

// ---------------- weight / codebook prep -------------------------------------------
__global__ void k_prep_w(const float* __restrict__ wctx, const float* __restrict__ wf1)
{
    int i = blockIdx.x * 256 + threadIdx.x;
    if (i < KC*DD) {
        int k = i / DD, o = i - k*DD;
        g_wT[i] = wctx[(size_t)o*KC + k];
    }
    if (i < 2*DD*DD) {
        int c = i / DD, o = i - c*DD;
        g_wf1T[i] = wf1[(size_t)o*(2*DD) + c];
    }
}
__global__ void k_prep_E(const float* __restrict__ E)
{
    int i = blockIdx.x * 256 + threadIdx.x;
    if (i < DD*MM) {
        int d = i / MM, m = i - d*MM;
        g_ET[i] = E[(size_t)m*DD + d];
        __nv_bfloat16 l0, l1, l2; split3(E[i], l0, l1, l2);
        g_EL[0][i] = l0; g_EL[1][i] = l1; g_EL[2][i] = l2;
    }
}
__global__ void k_prep_wf2(const float* __restrict__ wf2)
{
    int i = blockIdx.x * 256 + threadIdx.x;
    if (i < DD*2*DD) {
        __nv_bfloat16 l0, l1, l2; split3(wf2[i], l0, l1, l2);
        g_wf2L[0][i] = l0; g_wf2L[1][i] = l1; g_wf2L[2][i] = l2;
    }
}
__global__ void k_e2(const float* __restrict__ E)
{
    int lane = threadIdx.x & 31, w = threadIdx.x >> 5;
    int m = blockIdx.x * 8 + w;
    const float* row = E + (size_t)m*DD;
    double s = 0.0;
    for (int k = lane; k < DD; k += 32) { float v = row[k]; s += (double)v*v; }
#pragma unroll
    for (int off = 16; off; off >>= 1) s += __shfl_down_sync(0xffffffffu, s, off);
    if (lane == 0) g_e2[m] = (float)s;
}

// ================= fp32 FFMA GEMMs, double-buffered (k-order == R9/R6) =============
#define FMA32() do { \
    acc[0][0] += a0.x*bv.x; acc[0][1] += a0.x*bv.y; acc[0][2] += a0.x*bv.z; acc[0][3] += a0.x*bv.w; \
    acc[1][0] += a0.y*bv.x; acc[1][1] += a0.y*bv.y; acc[1][2] += a0.y*bv.z; acc[1][3] += a0.y*bv.w; \
    acc[2][0] += a0.z*bv.x; acc[2][1] += a0.z*bv.y; acc[2][2] += a0.z*bv.z; acc[2][3] += a0.z*bv.w; \
    acc[3][0] += a0.w*bv.x; acc[3][1] += a0.w*bv.y; acc[3][2] += a0.w*bv.z; acc[3][3] += a0.w*bv.w; \
    acc[4][0] += a1.x*bv.x; acc[4][1] += a1.x*bv.y; acc[4][2] += a1.x*bv.z; acc[4][3] += a1.x*bv.w; \
    acc[5][0] += a1.y*bv.x; acc[5][1] += a1.y*bv.y; acc[5][2] += a1.y*bv.z; acc[5][3] += a1.y*bv.w; \
    acc[6][0] += a1.z*bv.x; acc[6][1] += a1.z*bv.y; acc[6][2] += a1.z*bv.z; acc[6][3] += a1.z*bv.w; \
    acc[7][0] += a1.w*bv.x; acc[7][1] += a1.w*bv.y; acc[7][2] += a1.w*bv.z; acc[7][3] += a1.w*bv.w; } while(0)

// ---------------- conv: ctx[bt][o] = sum_k cn[t + k%7][k/7] * wT[k][o] -------------
// Prefetch addresses via incremental (i,h) update: k += 16 => off += 2*TJ+2 (+TJ-7 on wrap)
__global__ void __launch_bounds__(256) k_conv()
{
    __shared__ float As[2][16][132];
    __shared__ float Bs[2][16][68];
    int b  = blockIdx.z;
    int t0 = blockIdx.y * 128;
    int o0 = blockIdx.x * 64;
    int tid = threadIdx.x;
    int tx = tid & 15, ty = tid >> 4;
    int lt = tid & 127, lk = tid >> 7;
    int bo = tid & 63,  bk = tid >> 6;
    const float* cbase = g_cn + (size_t)b*DD*TJ + t0 + lt;
    float acc[8][4] = {};
    float pa[8], pb[4];
    int hh[8], off[8];
#pragma unroll
    for (int p = 0; p < 8; p++) {
        int k = lk + p*2;
        int i = k / 7;
        hh[p]  = k - i*7;
        off[p] = i*TJ + hh[p];
        pa[p]  = cbase[off[p]];
    }
#pragma unroll
    for (int p = 0; p < 4; p++)
        pb[p] = g_wT[(size_t)(bk + p*4)*DD + o0 + bo];
    const int NIT = KC/16;
    for (int it = 0; it < NIT; it++) {
        int buf = it & 1;
#pragma unroll
        for (int p = 0; p < 8; p++) As[buf][lk + p*2][lt] = pa[p];
#pragma unroll
        for (int p = 0; p < 4; p++) Bs[buf][bk + p*4][bo] = pb[p];
        __syncthreads();
        if (it + 1 < NIT) {
            int k0 = (it+1)*16;
#pragma unroll
            for (int p = 0; p < 8; p++) {
                hh[p] += 2; off[p] += 2*TJ + 2;
                if (hh[p] >= 7) { hh[p] -= 7; off[p] += TJ - 7; }
                pa[p] = cbase[off[p]];
            }
#pragma unroll
            for (int p = 0; p < 4; p++)
                pb[p] = g_wT[(size_t)(k0 + bk + p*4)*DD + o0 + bo];
        }
#pragma unroll
        for (int kk = 0; kk < 16; kk++) {
            float4 a0 = *reinterpret_cast<const float4*>(&As[buf][kk][ty*8]);
            float4 a1 = *reinterpret_cast<const float4*>(&As[buf][kk][ty*8 + 4]);
            float4 bv = *reinterpret_cast<const float4*>(&Bs[buf][kk][tx*4]);
            FMA32();
        }
    }
#pragma unroll
    for (int i = 0; i < 8; i++) {
        size_t base = ((size_t)b*TT + t0 + ty*8 + i)*DD + o0 + tx*4;
        float4 v = make_float4(acc[i][0], acc[i][1], acc[i][2], acc[i][3]);
        *reinterpret_cast<float4*>(&g_ctxT[base]) = v;
        __nv_bfloat16 p0,p1,p2,q0,q1,q2;
        split3(v.x, p0, p1, p2); split3(v.y, q0, q1, q2);
        __nv_bfloat162 t;
        t.x = p0; t.y = q0; *reinterpret_cast<__nv_bfloat162*>(&g_ctxL[0][base]) = t;
        t.x = p1; t.y = q1; *reinterpret_cast<__nv_bfloat162*>(&g_ctxL[1][base]) = t;
        t.x = p2; t.y = q2; *reinterpret_cast<__nv_bfloat162*>(&g_ctxL[2][base]) = t;
        split3(v.z, p0, p1, p2); split3(v.w, q0, q1, q2);
        t.x = p0; t.y = q0; *reinterpret_cast<__nv_bfloat162*>(&g_ctxL[0][base + 2]) = t;
        t.x = p1; t.y = q1; *reinterpret_cast<__nv_bfloat162*>(&g_ctxL[1][base + 2]) = t;
        t.x = p2; t.y = q2; *reinterpret_cast<__nv_bfloat162*>(&g_ctxL[2][base + 2]) = t;
    }
}

// ---------------- fuse1: cur = PReLU(wf1 . [x | ctx], a1) --------------------------
__global__ void __launch_bounds__(256) k_fuse1(const float* __restrict__ x,
                                               const float* __restrict__ a_ptr)
{
    __shared__ float As[2][16][132];
    __shared__ float Bs[2][16][68];
    int b  = blockIdx.z;
    int t0 = blockIdx.y * 128;
    int o0 = blockIdx.x * 64;
    int tid = threadIdx.x;
    int tx = tid & 15, ty = tid >> 4;
    int aK = tid & 15, aT = tid >> 4;
    int bo = tid & 63, bk = tid >> 6;
    const float* xb   = x      + ((size_t)b*TT + t0)*DD;
    const float* ctxb = g_ctxT + ((size_t)b*TT + t0)*DD;
    float acc[8][4] = {};
    float pa[8], pb[4];
#pragma unroll
    for (int p = 0; p < 8; p++)
        pa[p] = xb[(size_t)(aT + p*16)*DD + aK];
#pragma unroll
    for (int p = 0; p < 4; p++)
        pb[p] = g_wf1T[(size_t)(bk + p*4)*DD + o0 + bo];
    const int NIT = (2*DD)/16;
    for (int it = 0; it < NIT; it++) {
        int buf = it & 1;
#pragma unroll
        for (int p = 0; p < 8; p++) As[buf][aK][aT + p*16] = pa[p];
#pragma unroll
        for (int p = 0; p < 4; p++) Bs[buf][bk + p*4][bo] = pb[p];
        __syncthreads();
        if (it + 1 < NIT) {
            int k0 = (it+1)*16;
            const float* src = (k0 < DD) ? xb : ctxb;
            int c = ((k0 < DD) ? k0 : k0 - DD) + aK;
#pragma unroll
            for (int p = 0; p < 8; p++)
                pa[p] = src[(size_t)(aT + p*16)*DD + c];
#pragma unroll
            for (int p = 0; p < 4; p++)
                pb[p] = g_wf1T[(size_t)(k0 + bk + p*4)*DD + o0 + bo];
        }
#pragma unroll
        for (int kk = 0; kk < 16; kk++) {
            float4 a0 = *reinterpret_cast<const float4*>(&As[buf][kk][ty*8]);
            float4 a1 = *reinterpret_cast<const float4*>(&As[buf][kk][ty*8 + 4]);
            float4 bv = *reinterpret_cast<const float4*>(&Bs[buf][kk][tx*4]);
            FMA32();
        }
    }
    float a = *a_ptr;
#pragma unroll
    for (int i = 0; i < 8; i++) {
        float4 v;
        float r;
        r = acc[i][0]; v.x = (r >= 0.f) ? r : a*r;
        r = acc[i][1]; v.y = (r >= 0.f) ? r : a*r;
        r = acc[i][2]; v.z = (r >= 0.f) ? r : a*r;
        r = acc[i][3]; v.w = (r >= 0.f) ? r : a*r;
        size_t base = ((size_t)b*TT + t0 + ty*8 + i)*DD + o0 + tx*4;
        *reinterpret_cast<float4*>(&g_cur[base]) = v;
    }
}

// ---------------- dist: z[r][m] = 2*cur.E_m - |E_m|^2 ------------------------------
__global__ void __launch_bounds__(256) k_dist()
{
    __shared__ float As[2][16][132];
    __shared__ float Bs[2][16][68];
    int r0 = blockIdx.y * 128;
    int m0 = blockIdx.x * 64;
    int tid = threadIdx.x;
    int tx = tid & 15, ty = tid >> 4;
    int aK = tid & 15, aT = tid >> 4;
    int bo = tid & 63, bk = tid >> 6;
    float acc[8][4] = {};
    float pa[8], pb[4];
#pragma unroll
    for (int p = 0; p < 8; p++)
        pa[p] = g_cur[(size_t)(r0 + aT + p*16)*DD + aK];
#pragma unroll
    for (int p = 0; p < 4; p++)
        pb[p] = g_ET[(size_t)(bk + p*4)*MM + m0 + bo];
    const int NIT = DD/16;
    for (int it = 0; it < NIT; it++) {
        int buf = it & 1;
#pragma unroll
        for (int p = 0; p < 8; p++) As[buf][aK][aT + p*16] = pa[p];
#pragma unroll
        for (int p = 0; p < 4; p++) Bs[buf][bk + p*4][bo] = pb[p];
        __syncthreads();
        if (it + 1 < NIT) {
            int k0 = (it+1)*16;
#pragma unroll
            for (int p = 0; p < 8; p++)
                pa[p] = g_cur[(size_t)(r0 + aT + p*16)*DD + k0 + aK];
#pragma unroll
            for (int p = 0; p < 4; p++)
                pb[p] = g_ET[(size_t)(k0 + bk + p*4)*MM + m0 + bo];
        }
#pragma unroll
        for (int kk = 0; kk < 16; kk++) {
            float4 a0 = *reinterpret_cast<const float4*>(&As[buf][kk][ty*8]);
            float4 a1 = *reinterpret_cast<const float4*>(&As[buf][kk][ty*8 + 4]);
            float4 bv = *reinterpret_cast<const float4*>(&Bs[buf][kk][tx*4]);
            FMA32();
        }
    }
    float e0 = g_e2[m0 + tx*4 + 0];
    float e1 = g_e2[m0 + tx*4 + 1];
    float e2v = g_e2[m0 + tx*4 + 2];
    float e3 = g_e2[m0 + tx*4 + 3];
#pragma unroll
    for (int i = 0; i < 8; i++) {
        float4 v;
        v.x = 2.0f*acc[i][0] - e0;
        v.y = 2.0f*acc[i][1] - e1;
        v.z = 2.0f*acc[i][2] - e2v;
        v.w = 2.0f*acc[i][3] - e3;
        *reinterpret_cast<float4*>(&g_z[(size_t)(r0 + ty*8 + i)*MM + m0 + tx*4]) = v;
    }
}

// ================= fuse2: HMMA bf16 limbs (output-only, 1e-3 budget) ===============
#define AS_ELE (128*40)
#define BS_ELE (64*40)
#define MMA16816(C, A0,A1,A2,A3, B0,B1) \
    asm volatile("mma.sync.aligned.m16n8k16.row.col.f32.bf16.bf16.f32 " \
        "{%0,%1,%2,%3}, {%4,%5,%6,%7}, {%8,%9}, {%0,%1,%2,%3};" \
        : "+f"((C)[0]), "+f"((C)[1]), "+f"((C)[2]), "+f"((C)[3]) \
        : "r"(A0), "r"(A1), "r"(A2), "r"(A3), "r"(B0), "r"(B1))

__device__ __forceinline__ void mma_chunk3(const __nv_bfloat16* As, const __nv_bfloat16* Bs,
                                           float acc[2][4][4], int wm, int wn, int lane)
{
    const int PA[3] = {0,0,1};
    const int PB[3] = {0,1,0};
    int rq = lane >> 2;
    int kq = (lane & 3) * 2;
#pragma unroll
    for (int p = 0; p < 3; p++) {
        const __nv_bfloat16* A = As + PA[p]*AS_ELE + (wm*32 + rq)*40;
        const __nv_bfloat16* B = Bs + PB[p]*BS_ELE + (wn*32 + rq)*40;
#pragma unroll
        for (int kk = 0; kk < 32; kk += 16) {
            uint32_t bfr[4][2];
#pragma unroll
            for (int nt = 0; nt < 4; nt++) {
                bfr[nt][0] = *(const uint32_t*)(B + nt*8*40 + kk + kq);
                bfr[nt][1] = *(const uint32_t*)(B + nt*8*40 + kk + kq + 8);
            }
#pragma unroll
            for (int mt = 0; mt < 2; mt++) {
                const __nv_bfloat16* Am = A + mt*16*40;
                uint32_t a0 = *(const uint32_t*)(Am + kk + kq);
                uint32_t a1 = *(const uint32_t*)(Am + 8*40 + kk + kq);
                uint32_t a2 = *(const uint32_t*)(Am + kk + kq + 8);
                uint32_t a3 = *(const uint32_t*)(Am + 8*40 + kk + kq + 8);
#pragma unroll
                for (int nt = 0; nt < 4; nt++)
                    MMA16816(acc[mt][nt], a0, a1, a2, a3, bfr[nt][0], bfr[nt][1]);
            }
        }
    }
}

__global__ void __launch_bounds__(256, 2) k_fuse2_mma(const float* __restrict__ a_ptr,
                                                      float* __restrict__ outq)
{
    __shared__ __nv_bfloat16 As[2*AS_ELE];
    __shared__ __nv_bfloat16 Bs[2*BS_ELE];
    __shared__ int sIdx[128];
    int tid = threadIdx.x, lane = tid & 31, wid = tid >> 5;
    int wm = wid >> 1, wn = wid & 1;
    int o0 = blockIdx.x * 64, t0 = blockIdx.y * 128, b = blockIdx.z;
    size_t bt0 = (size_t)b*TT + t0;
    if (tid < 128) sIdx[tid] = g_idx[b*TT + t0 + tid];
    __syncthreads();
    float acc[2][4][4] = {};
    for (int ch = 0; ch < 16; ch++) {
        int k0 = (ch & 7) * 32;
#pragma unroll
        for (int q = 0; q < 8; q++) {
            int j = tid + 256*q;
            int row = j >> 4, c2 = (j & 15) * 2;
            size_t src;
            if (ch < 8) src = (size_t)sIdx[row]*DD + k0 + c2;
            else        src = (bt0 + row)*DD + k0 + c2;
            int d = row*40 + c2;
            const __nv_bfloat16* L0 = (ch < 8) ? g_EL[0] : g_ctxL[0];
            const __nv_bfloat16* L1 = (ch < 8) ? g_EL[1] : g_ctxL[1];
            *(uint32_t*)(As + 0*AS_ELE + d) = *(const uint32_t*)(L0 + src);
            *(uint32_t*)(As + 1*AS_ELE + d) = *(const uint32_t*)(L1 + src);
        }
#pragma unroll
        for (int q = 0; q < 4; q++) {
            int j = tid + 256*q;
            int row = j >> 4, c2 = (j & 15) * 2;
            size_t src = (size_t)(o0 + row)*(2*DD) + ch*32 + c2;
            int d = row*40 + c2;
            *(uint32_t*)(Bs + 0*BS_ELE + d) = *(const uint32_t*)(g_wf2L[0] + src);
            *(uint32_t*)(Bs + 1*BS_ELE + d) = *(const uint32_t*)(g_wf2L[1] + src);
        }
        __syncthreads();
        mma_chunk3(As, Bs, acc, wm, wn, lane);
        __syncthreads();
    }
    float a = *a_ptr;
    int rq = lane >> 2, cq = (lane & 3) * 2;
#pragma unroll
    for (int mt = 0; mt < 2; mt++)
#pragma unroll
    for (int nt = 0; nt < 4; nt++) {
        int row = wm*32 + mt*16 + rq;
        int col = o0 + wn*32 + nt*8 + cq;
#pragma unroll
        for (int hh = 0; hh < 2; hh++) {
            float v0 = acc[mt][nt][hh*2 + 0];
            float v1 = acc[mt][nt][hh*2 + 1];
            v0 = (v0 >= 0.f) ? v0 : a*v0;
            v1 = (v1 >= 0.f) ? v1 : a*v1;
            size_t base = (bt0 + row + hh*8)*DD + col;
            *(float2*)(outq + base) = make_float2(v0, v1);
        }
    }
}

// ---------------- warp helpers -----------------------------------------------------
__device__ __forceinline__ void wargmax(float& v, int& i)
{
#pragma unroll
    for (int off = 16; off; off >>= 1) {
        float ov = __shfl_down_sync(0xffffffffu, v, off);
        int   oi = __shfl_down_sync(0xffffffffu, i, off);
        if (ov > v || (ov == v && oi < i)) { v = ov; i = oi; }
    }
}

// ---------------- K4b: warp-per-row argmax / softmax / gumbel ----------------------
// 512 blocks x 8 warps x 8 rows. Elementwise math identical to R12 (same formulas,
// same min-index tie-break); only reduction topology changed (shuffle-only).
__global__ void __launch_bounds__(256) k_stats(const float* __restrict__ gu,
                                               float* __restrict__ out_inds,
                                               int write_inds)
{
    __shared__ float sAcc[8][MM];
    __shared__ int   sHist[MM];
    int tid = threadIdx.x, lane = tid & 31, w = tid >> 5;
    for (int q = tid; q < MM; q += 256) sHist[q] = 0;
    float acc[32];
#pragma unroll
    for (int k = 0; k < 32; k++) acc[k] = 0.f;
    __syncthreads();
    int rbase = blockIdx.x * 64 + w * 8;
    for (int r = 0; r < 8; r++) {
        int row = rbase + r;
        const float4* zr = reinterpret_cast<const float4*>(g_z + (size_t)row*MM);
        const float4* ur = reinterpret_cast<const float4*>(gu  + (size_t)row*MM);
        float zs[32];
        float hv = -FLT_MAX; int hi = 0x7fffffff;
        float yv = -FLT_MAX; int yi = 0x7fffffff;
        const float lo = 1e-10f, hicl = 1.0f - 1e-7f;
#pragma unroll
        for (int q = 0; q < 8; q++) {
            float4 z = zr[q*32 + lane];
            float4 u = ur[q*32 + lane];
            int m0 = q*128 + lane*4;
            zs[q*4+0] = z.x; zs[q*4+1] = z.y; zs[q*4+2] = z.z; zs[q*4+3] = z.w;
            if (z.x > hv) { hv = z.x; hi = m0; }
            if (z.y > hv) { hv = z.y; hi = m0+1; }
            if (z.z > hv) { hv = z.z; hi = m0+2; }
            if (z.w > hv) { hv = z.w; hi = m0+3; }
            float y0 = z.x - __logf(-logf(fminf(fmaxf(u.x, lo), hicl)));
            float y1 = z.y - __logf(-logf(fminf(fmaxf(u.y, lo), hicl)));
            float y2 = z.z - __logf(-logf(fminf(fmaxf(u.z, lo), hicl)));
            float y3 = z.w - __logf(-logf(fminf(fmaxf(u.w, lo), hicl)));
            if (y0 > yv) { yv = y0; yi = m0; }
            if (y1 > yv) { yv = y1; yi = m0+1; }
            if (y2 > yv) { yv = y2; yi = m0+2; }
            if (y3 > yv) { yv = y3; yi = m0+3; }
        }
        wargmax(hv, hi);
        wargmax(yv, yi);
        float mx  = __shfl_sync(0xffffffffu, hv, 0);
        int hIdx  = __shfl_sync(0xffffffffu, hi, 0);
        int yIdx  = __shfl_sync(0xffffffffu, yi, 0);
        if (lane == 0) {
            atomicAdd(&sHist[hIdx], 1);          // integer atomic: deterministic
            g_idx[row] = yIdx;
            if (write_inds) out_inds[row] = (float)yIdx;
        }
        float s = 0.f;
#pragma unroll
        for (int k = 0; k < 32; k++) { zs[k] = __expf(zs[k] - mx); s += zs[k]; }
#pragma unroll
        for (int off = 16; off; off >>= 1) s += __shfl_xor_sync(0xffffffffu, s, off);
        float inv = 1.0f / s;
#pragma unroll
        for (int k = 0; k < 32; k++) acc[k] += zs[k]*inv;
    }
#pragma unroll
    for (int q = 0; q < 8; q++)
        *reinterpret_cast<float4*>(&sAcc[w][q*128 + lane*4]) =
            make_float4(acc[q*4], acc[q*4+1], acc[q*4+2], acc[q*4+3]);
    __syncthreads();
    // combine 8 warp partials in fixed order; 256 threads x 4 cols = 1024 cols
    {
        int m = tid * 4;
        float4 t = *reinterpret_cast<float4*>(&sAcc[0][m]);
#pragma unroll
        for (int ww = 1; ww < 8; ww++) {
            float4 o = *reinterpret_cast<float4*>(&sAcc[ww][m]);
            t.x += o.x; t.y += o.y; t.z += o.z; t.w += o.w;
        }
        *reinterpret_cast<float4*>(&g_avgp[(size_t)blockIdx.x*MM + m]) = t;
        int4 hv4 = *reinterpret_cast<int4*>(&sHist[m]);
        *reinterpret_cast<int4*>(&g_hardp[(size_t)blockIdx.x*MM + m]) = hv4;
    }
}

// ---------------- K5: entropy reductions -------------------------------------------
__global__ void k_colred()
{
    int m = blockIdx.x;
    int tid = threadIdx.x;
    __shared__ float shf[256];
    __shared__ int   shi[256];
    shf[tid] = g_avgp[(size_t)tid*MM + m] + g_avgp[(size_t)(tid + 256)*MM + m];
    shi[tid] = g_hardp[(size_t)tid*MM + m] + g_hardp[(size_t)(tid + 256)*MM + m];
    __syncthreads();
    for (int st = 128; st; st >>= 1) {
        if (tid < st) { shf[tid] += shf[tid+st]; shi[tid] += shi[tid+st]; }
        __syncthreads();
    }
    if (tid == 0) {
        float ap = shf[0] / (float)NROWS;
        float hp = (float)shi[0] / (float)NROWS;
        g_terms[m]      = -ap * log2f(ap + 1e-10f);
        g_terms[MM + m] = -hp * log2f(hp + 1e-10f);
    }
}
__global__ void k_final(float* __restrict__ out, int write_ok)
{
    __shared__ float s1[256], s2[256];
    int tid = threadIdx.x;
    float a = 0.f, b = 0.f;
    for (int m = tid; m < MM; m += 256) { a += g_terms[m]; b += g_terms[MM + m]; }
    s1[tid] = a; s2[tid] = b; __syncthreads();
    for (int st = 128; st; st >>= 1) {
        if (tid < st) { s1[tid] += s1[tid+st]; s2[tid] += s2[tid+st]; }
        __syncthreads();
    }
    if (tid == 0 && write_ok) {
        out[QOUT + 0] = s2[0];   // code_perplexity (hard)
        out[QOUT + 1] = s1[0];   // prob_perplexity (soft)
    }
}

// ---------------- launch (k_conv at slot 4 for ncu capture) ------------------------
extern "C" void kernel_launch(void* const* d_in, const int* in_sizes, int n_in,
                              void* d_out, int out_size)
{
    const float* x     = (const float*)d_in[0];
    const float* noise = (const float*)d_in[1];
    const float* gu    = (const float*)d_in[2];
    const int*   epo   = (const int*)  d_in[3];
    const float* E     = (const float*)d_in[4];
    const float* wctx  = (const float*)d_in[5];
    const float* wf1   = (const float*)d_in[6];
    const float* a1    = (const float*)d_in[7];
    const float* wf2   = (const float*)d_in[8];
    const float* a2    = (const float*)d_in[9];
    float* out = (float*)d_out;
    int tail_ok = (out_size >= OUT_NEED) ? 1 : 0;

    k_scale<<<BB, 256>>>(x, epo);                               // 1
    k_prep_w<<<(KC*DD + 255)/256, 256>>>(wctx, wf1);            // 2
    k_cn<<<dim3((TJ + 31)/32, DD/32, BB), dim3(32, 8)>>>(x, noise); // 3
    k_conv <<<dim3(DD/64, TT/128, BB), 256>>>();                // 4 <- ncu capture slot
    k_prep_E<<<(DD*MM)/256, 256>>>(E);                          // 5
    k_e2<<<MM/8, 256>>>(E);                                     // 6
    k_fuse1<<<dim3(DD/64, TT/128, BB), 256>>>(x, a1);           // 7
    k_dist <<<dim3(MM/64, NROWS/128), 256>>>();                 // 8
    k_prep_wf2<<<(DD*2*DD)/256, 256>>>(wf2);                    // 9
    k_stats<<<NSB, 256>>>(gu, out + QOUT + 2, tail_ok);         // 10
    k_colred<<<MM, 256>>>();                                    // 11
    k_final<<<1, 256>>>(out, tail_ok);                          // 12
    k_fuse2_mma<<<dim3(DD/64, TT/128, BB), 256>>>(a2, out);     // 13
}